// round 8
// baseline (speedup 1.0000x reference)
#include <cuda_runtime.h>
#include <cuda_bf16.h>
#include <math.h>
#include <cstdint>

#define Lc   8
#define Bc   4
#define Sc   2048
#define Dc   256
#define SDc  512
#define Mc   (Bc*Sc)      // 8192

#define K1   1536         // W1 k-dim: [Whi|Wlo|Whi] x 512
#define N1   1536         // 1024 (Bx interleaved) + 512 (gate)
#define K2   4608         // W2 k-dim: hall [Whi|Wlo|Whi]x1024 + xn [Whi|Wlo|Whi]x512
#define N2   512          // interleaved y pairs
#define KA1  1024         // A1 storage: [xn_hi 512 | xn_lo 512]
#define KA2  2048         // A2 storage: [hall_hi 1024 | hall_lo 1024]
#define NCH  64
#define CHLEN 32

// ----------------------------- device scratch --------------------------------
__device__ __nv_bfloat16 g_A1[(size_t)Mc*KA1];
__device__ __nv_bfloat16 g_A2[(size_t)Mc*KA2];
__device__ __nv_bfloat16 g_W1[(size_t)Lc*N1*K1];   // [l][n][k]
__device__ __nv_bfloat16 g_W2[(size_t)Lc*N2*K2];   // [l][n][k]
__device__ float g_Bx[(size_t)Mc*1024];            // interleaved (bxr,bxi)
__device__ float g_gt[(size_t)Mc*512];
__device__ float g_h [(size_t)Mc*512];             // interleaved activation
__device__ float g_carry[(size_t)NCH*Bc*SDc*4];
__device__ float g_hst  [(size_t)NCH*Bc*SDc*2];

// ----------------------------- helpers ----------------------------------------
__device__ __forceinline__ uint32_t s2u(const void* p){
    uint32_t a;
    asm("{ .reg .u64 t; cvta.to.shared.u64 t, %1; cvt.u32.u64 %0, t; }" : "=r"(a) : "l"(p));
    return a;
}
__device__ __forceinline__ void cpa16(uint32_t s, const void* g){
    asm volatile("cp.async.cg.shared.global [%0], [%1], 16;" :: "r"(s), "l"(g));
}
__device__ __forceinline__ uint32_t swz(uint32_t o){ return o ^ ((o >> 3) & 0x70); }

__device__ __forceinline__ void ldsm4(uint32_t* r, uint32_t addr){
    asm volatile("ldmatrix.sync.aligned.m8n8.x4.shared.b16 {%0,%1,%2,%3}, [%4];"
        : "=r"(r[0]), "=r"(r[1]), "=r"(r[2]), "=r"(r[3]) : "r"(addr));
}
__device__ __forceinline__ void mma16816(float* d, const uint32_t* a, const uint32_t* b){
    asm volatile("mma.sync.aligned.m16n8k16.row.col.f32.bf16.bf16.f32 "
        "{%0,%1,%2,%3}, {%4,%5,%6,%7}, {%8,%9}, {%0,%1,%2,%3};"
        : "+f"(d[0]), "+f"(d[1]), "+f"(d[2]), "+f"(d[3])
        : "r"(a[0]), "r"(a[1]), "r"(a[2]), "r"(a[3]), "r"(b[0]), "r"(b[1]));
}

// ----------------------------- weight prep ------------------------------------
__global__ void prep_w1(const float* __restrict__ BWr, const float* __restrict__ BWi,
                        const float* __restrict__ gW)
{
    size_t i = (size_t)blockIdx.x * blockDim.x + threadIdx.x;
    if (i >= (size_t)Lc*N1*K1) return;
    int k = (int)(i % K1); size_t r = i / K1; int n = (int)(r % N1); int l = (int)(r / N1);
    int blk = k / 512, kk = k % 512;
    float v;
    if (n < 1024) {
        int j = n >> 1, p = n & 1;
        if (kk < 256) v = p ? BWi[((size_t)l*256+kk)*512+j] : BWr[((size_t)l*256+kk)*512+j];
        else { int kr = kk-256; v = p ? BWr[((size_t)l*256+kr)*512+j] : -BWi[((size_t)l*256+kr)*512+j]; }
    } else {
        v = gW[((size_t)l*512+kk)*512 + (n-1024)];
    }
    __nv_bfloat16 hi = __float2bfloat16(v);
    g_W1[i] = (blk == 1) ? __float2bfloat16(v - __bfloat162float(hi)) : hi;
}

__global__ void prep_w2(const float* __restrict__ CWr, const float* __restrict__ CWi,
                        const float* __restrict__ DWr, const float* __restrict__ DWi)
{
    size_t i = (size_t)blockIdx.x * blockDim.x + threadIdx.x;
    if (i >= (size_t)Lc*N2*K2) return;
    int k = (int)(i % K2); size_t r = i / K2; int n = (int)(r % N2); int l = (int)(r / N2);
    int j = n >> 1, p = n & 1;
    float v; int blk;
    if (k < 3072) {
        blk = k / 1024; int kk = k % 1024;
        if (kk < 512) v = p ? CWi[((size_t)l*512+kk)*256+j] : CWr[((size_t)l*512+kk)*256+j];
        else { int ki = kk-512; v = p ? CWr[((size_t)l*512+ki)*256+j] : -CWi[((size_t)l*512+ki)*256+j]; }
    } else {
        int k2 = k - 3072; blk = k2 / 512; int kk = k2 % 512;
        if (kk < 256) v = p ? DWi[((size_t)l*256+kk)*256+j] : DWr[((size_t)l*256+kk)*256+j];
        else { int kr = kk-256; v = p ? DWr[((size_t)l*256+kr)*256+j] : -DWi[((size_t)l*256+kr)*256+j]; }
    }
    __nv_bfloat16 hi = __float2bfloat16(v);
    g_W2[i] = (blk == 1) ? __float2bfloat16(v - __bfloat162float(hi)) : hi;
}

// ----------------------------- LayerNorm (warp per row) ------------------------
__global__ void ln_kernel(const float* __restrict__ src,
                          const float* __restrict__ gw, const float* __restrict__ bw,
                          int final_mode, float* __restrict__ outInter)
{
    int warp = threadIdx.x >> 5, L = threadIdx.x & 31;
    int m = blockIdx.x * 8 + warp;
    const float4* row = (const float4*)(src + (size_t)m * 512);
    float4 v[4];
    float sr=0.f, si=0.f, qr=0.f, qi=0.f;
    #pragma unroll
    for (int j=0;j<4;j++){
        v[j] = row[L + 32*j];
        sr += v[j].x + v[j].z;  si += v[j].y + v[j].w;
        qr += v[j].x*v[j].x + v[j].z*v[j].z;
        qi += v[j].y*v[j].y + v[j].w*v[j].w;
    }
    #pragma unroll
    for (int o=16;o>0;o>>=1){
        sr += __shfl_xor_sync(0xffffffffu, sr, o);
        si += __shfl_xor_sync(0xffffffffu, si, o);
        qr += __shfl_xor_sync(0xffffffffu, qr, o);
        qi += __shfl_xor_sync(0xffffffffu, qi, o);
    }
    const float inv = 1.f/256.f;
    float mur = sr*inv, mui = si*inv;
    float isr = rsqrtf(qr*inv - mur*mur + 1e-5f);
    float isi = rsqrtf(qi*inv - mui*mui + 1e-5f);

    __nv_bfloat16* a1 = g_A1 + (size_t)m * KA1;
    float* ointer = final_mode ? (outInter + (size_t)m*512) : nullptr;

    #pragma unroll
    for (int j=0;j<4;j++){
        int f = L + 32*j;
        float2 g2 = ((const float2*)gw)[f];
        float2 b2 = ((const float2*)bw)[f];
        float nr0 = (v[j].x - mur)*isr*g2.x + b2.x;
        float ni0 = (v[j].y - mui)*isi*g2.x + b2.x;
        float nr1 = (v[j].z - mur)*isr*g2.y + b2.y;
        float ni1 = (v[j].w - mui)*isi*g2.y + b2.y;
        if (final_mode) {
            float4 o4; o4.x=nr0; o4.y=ni0; o4.z=nr1; o4.w=ni1;
            ((float4*)ointer)[f] = o4;
        } else {
            int d0 = 2*f;
            __nv_bfloat162 rh = __floats2bfloat162_rn(nr0, nr1);
            __nv_bfloat162 ih = __floats2bfloat162_rn(ni0, ni1);
            __nv_bfloat162 rl = __floats2bfloat162_rn(nr0 - __bfloat162float(rh.x),
                                                      nr1 - __bfloat162float(rh.y));
            __nv_bfloat162 il = __floats2bfloat162_rn(ni0 - __bfloat162float(ih.x),
                                                      ni1 - __bfloat162float(ih.y));
            *(__nv_bfloat162*)(a1 + d0)       = rh;
            *(__nv_bfloat162*)(a1 + 256 + d0) = ih;
            *(__nv_bfloat162*)(a1 + 512 + d0) = rl;
            *(__nv_bfloat162*)(a1 + 768 + d0) = il;
        }
    }
}

// ----------------------------- scan (chunked) ----------------------------------
__global__ void scan1(int layer, const float* __restrict__ theta, const float* __restrict__ damp)
{
    int t = blockIdx.x*blockDim.x + threadIdx.x;   // 131072
    int sd = t & 511, ch = (t >> 9) & 63, b = t >> 15;
    float th = theta[layer*SDc+sd], dp = damp[layer*SDc+sd];
    float dm = 0.5f + 0.5f/(1.f+expf(-dp));
    float cd = cosf(th)*dm, sn = sinf(th)*dm;
    float Ar=1.f, Ai=0.f, Br=0.f, Bi=0.f;
    int base_row = b*Sc + ch*CHLEN;
    for (int s=0;s<CHLEN;s++){
        int row = base_row + s;
        float g = g_gt[(size_t)row*512+sd];
        float2 bx = *(const float2*)&g_Bx[(size_t)row*1024 + 2*sd];
        float og = 1.f - g;
        float ar = og*cd, ai = og*sn;
        float nAr = ar*Ar - ai*Ai, nAi = ar*Ai + ai*Ar;
        float nBr = ar*Br - ai*Bi + g*bx.x;
        float nBi = ar*Bi + ai*Br + g*bx.y;
        Ar=nAr; Ai=nAi; Br=nBr; Bi=nBi;
    }
    size_t o = ((size_t)ch*Bc*SDc + (size_t)b*SDc + sd)*4;
    float4 cc; cc.x=Ar; cc.y=Ai; cc.z=Br; cc.w=Bi;
    *(float4*)&g_carry[o] = cc;
}

__global__ void scan2(int layer, const float* __restrict__ h0, float* __restrict__ hfin)
{
    int t = blockIdx.x*blockDim.x + threadIdx.x;
    if (t >= Bc*SDc) return;
    int b = t / SDc, sd = t % SDc;
    size_t hidx = ((size_t)(layer*Bc+b)*SDc + sd)*2;
    float hr = h0[hidx], hi = h0[hidx+1];
    for (int ch = 0; ch < NCH; ch++){
        size_t o = (size_t)ch*Bc*SDc + t;
        g_hst[o*2] = hr; g_hst[o*2+1] = hi;
        float4 cc = *(const float4*)&g_carry[o*4];
        float nr = cc.x*hr - cc.y*hi + cc.z;
        float ni = cc.x*hi + cc.y*hr + cc.w;
        hr = nr; hi = ni;
    }
    hfin[hidx] = hr; hfin[hidx+1] = hi;
}

__global__ void scan3(int layer, const float* __restrict__ theta, const float* __restrict__ damp)
{
    int t = blockIdx.x*blockDim.x + threadIdx.x;
    int sd = t & 511, ch = (t >> 9) & 63, b = t >> 15;
    float th = theta[layer*SDc+sd], dp = damp[layer*SDc+sd];
    float dm = 0.5f + 0.5f/(1.f+expf(-dp));
    float cd = cosf(th)*dm, sn = sinf(th)*dm;
    size_t o = (size_t)ch*Bc*SDc + (size_t)b*SDc + sd;
    float hr = g_hst[o*2], hi = g_hst[o*2+1];
    int base_row = b*Sc + ch*CHLEN;
    for (int s=0;s<CHLEN;s++){
        int row = base_row + s;
        float g = g_gt[(size_t)row*512+sd];
        float2 bx = *(const float2*)&g_Bx[(size_t)row*1024 + 2*sd];
        float tr = hr*cd - hi*sn, ti = hr*sn + hi*cd;
        float og = 1.f - g;
        hr = fmaf(g, bx.x, og*tr);
        hi = fmaf(g, bx.y, og*ti);
        __nv_bfloat16 hh = __float2bfloat16(hr);
        __nv_bfloat16 hl = __float2bfloat16(hr - __bfloat162float(hh));
        __nv_bfloat16 ih = __float2bfloat16(hi);
        __nv_bfloat16 il = __float2bfloat16(hi - __bfloat162float(ih));
        __nv_bfloat16* a2 = g_A2 + (size_t)row*KA2;
        a2[sd]=hh; a2[512+sd]=ih; a2[1024+sd]=hl; a2[1536+sd]=il;
    }
}

// ----------------------------- HMMA GEMM ---------------------------------------
// 128x256 CTA tile, 512 threads (2x8 warps, 64x32 each), BK=64, 3-stage cp.async.
// W is [n][KW], KW = 3*Ks blocks [Whi|Wlo|Whi]; A deduped [Ahi|Alo], remapped.
// Regions: ki < hallIters -> A2 (stride 2048, 16 blocks); else A1 (stride 1024, 8).
// mode 0: n<1024 -> oBx; n>=1024 -> oGt = sigmoid(v + gb)
// mode 1: pairs (2j,2j+1)=(yr,yi): hOut = resid + 0.1*(yr*y + y)
#define ST 3
#define A_BYTES 16384
#define B_BYTES 32768
#define STAGE_BYTES (A_BYTES + B_BYTES)    // 48KB
#define GEMM_SMEM (ST*STAGE_BYTES)         // 144KB

__global__ void __launch_bounds__(512, 1)
mma_gemm(const __nv_bfloat16* __restrict__ A1p, const __nv_bfloat16* __restrict__ A2p,
         const __nv_bfloat16* __restrict__ W, int KW, int hallIters, int mode,
         float* __restrict__ oBx, float* __restrict__ oGt, const float* __restrict__ gb,
         const float* __restrict__ resid, float* __restrict__ hOut)
{
    extern __shared__ char smem[];
    uint32_t sb = s2u(smem);
    int tid = threadIdx.x, wid = tid >> 5, L = tid & 31;
    int m0 = blockIdx.y * 128, n0 = blockIdx.x * 256;
    const int NK = KW >> 6;

    // ---- A chunks (2 x 16B per thread per stage; 1024 chunks total) ----
    uint32_t rA[2], cA[2], soffA[2];
    #pragma unroll
    for (int i = 0; i < 2; i++) {
        int q = tid + i*512;              // 0..1023
        int r = q >> 3, c = q & 7;
        rA[i] = (uint32_t)(m0 + r);
        cA[i] = (uint32_t)(c * 8);
        soffA[i] = swz((uint32_t)(r*128 + c*16));
    }
    // ---- B chunks (4 x 16B per thread; 2048 chunks, 256 rows) ----
    const __nv_bfloat16* gBp[4]; uint32_t soffB[4];
    #pragma unroll
    for (int i = 0; i < 4; i++) {
        int q = tid + i*512;              // 0..2047
        int r = q >> 3, c = q & 7;
        gBp[i] = W + (size_t)(n0 + r)*KW + c*8;
        soffB[i] = (uint32_t)A_BYTES + swz((uint32_t)(r*128 + c*16));
    }

    // ---- ldmatrix lane addressing (SW128) ----
    int wm = wid >> 3, wn = wid & 7;      // 2 x 8 warps
    int rowA0 = wm*64 + (L & 7) + ((L >> 3) & 1) * 8;
    uint32_t aBase = (uint32_t)rowA0 * 128; uint32_t aS = (uint32_t)(rowA0 & 7);
    uint32_t aC = (uint32_t)(L >> 4);
    int rowB0 = wn*32 + (L & 7) + ((L >> 4) & 1) * 8;
    uint32_t bBase = (uint32_t)A_BYTES + (uint32_t)rowB0 * 128; uint32_t bS = (uint32_t)(rowB0 & 7);
    uint32_t bC = (uint32_t)((L >> 3) & 1);

    float c[4][4][4];
    #pragma unroll
    for (int i=0;i<4;i++)
        #pragma unroll
        for (int j=0;j<4;j++)
            #pragma unroll
            for (int e=0;e<4;e++) c[i][j][e] = 0.f;

    // stage loader
    auto load_stage = [&](int ki, uint32_t st){
        int j, nb, sh; const __nv_bfloat16* ab;
        if (ki < hallIters) { j = ki; nb = 16; sh = 11; ab = A2p; }
        else { j = ki - hallIters; nb = 8; sh = 10; ab = A1p; }
        uint32_t koff = (uint32_t)(((j < nb) ? j : j - nb) << 6);
        #pragma unroll
        for (int i = 0; i < 2; i++)
            cpa16(st + soffA[i], ab + ((rA[i] << sh) + koff + cA[i]));
        uint32_t kb = (uint32_t)(ki * 64);
        #pragma unroll
        for (int i = 0; i < 4; i++)
            cpa16(st + soffB[i], gBp[i] + kb);
    };

    // ---- prologue: load stages 0,1 ----
    #pragma unroll
    for (int s = 0; s < ST-1; s++) {
        if (s < NK) load_stage(s, sb + s*STAGE_BYTES);
        asm volatile("cp.async.commit_group;" ::: "memory");
    }

    for (int ki = 0; ki < NK; ki++) {
        asm volatile("cp.async.wait_group %0;" :: "n"(ST-2) : "memory");
        __syncthreads();

        uint32_t st = sb + (uint32_t)(ki % ST) * STAGE_BYTES;
        #pragma unroll
        for (int kk = 0; kk < 4; kk++) {
            uint32_t a[4][4], b[2][4];
            uint32_t ca = (uint32_t)(kk*2);
            #pragma unroll
            for (int mt = 0; mt < 4; mt++)
                ldsm4(a[mt], st + aBase + (uint32_t)mt*2048 + (((ca + aC) ^ aS) << 4));
            #pragma unroll
            for (int bt = 0; bt < 2; bt++)
                ldsm4(b[bt], st + bBase + (uint32_t)bt*2048 + (((ca + bC) ^ bS) << 4));
            #pragma unroll
            for (int mt = 0; mt < 4; mt++)
                #pragma unroll
                for (int nt = 0; nt < 4; nt++)
                    mma16816(c[mt][nt], a[mt], &b[nt>>1][(nt&1)*2]);
        }

        int ls = ki + ST - 1;
        if (ls < NK) load_stage(ls, sb + (uint32_t)(ls % ST) * STAGE_BYTES);
        asm volatile("cp.async.commit_group;" ::: "memory");
    }

    // ---- epilogue: direct float2 stores ----
    int lrow = L >> 2, lcol = (L & 3) * 2;
    int mRow = m0 + wm*64 + lrow;
    int nCol = n0 + wn*32 + lcol;
    #pragma unroll
    for (int mt = 0; mt < 4; mt++) {
        #pragma unroll
        for (int nt = 0; nt < 4; nt++) {
            int row = mRow + mt*16;
            int col = nCol + nt*8;
            float* cc = c[mt][nt];
            if (mode == 0) {
                if (col < 1024) {
                    float2 v0; v0.x = cc[0]; v0.y = cc[1];
                    float2 v1; v1.x = cc[2]; v1.y = cc[3];
                    *(float2*)&oBx[(size_t)row*1024 + col] = v0;
                    *(float2*)&oBx[(size_t)(row+8)*1024 + col] = v1;
                } else {
                    int gc = col - 1024;
                    float b0 = gb[gc], b1 = gb[gc+1];
                    float2 v0, v1;
                    v0.x = 1.f/(1.f+expf(-(cc[0]+b0)));
                    v0.y = 1.f/(1.f+expf(-(cc[1]+b1)));
                    v1.x = 1.f/(1.f+expf(-(cc[2]+b0)));
                    v1.y = 1.f/(1.f+expf(-(cc[3]+b1)));
                    *(float2*)&oGt[(size_t)row*512 + gc] = v0;
                    *(float2*)&oGt[(size_t)(row+8)*512 + gc] = v1;
                }
            } else {
                float2 r0 = *(const float2*)&resid[(size_t)row*512 + col];
                float2 r1 = *(const float2*)&resid[(size_t)(row+8)*512 + col];
                float2 v0, v1;
                v0.x = r0.x + 0.1f*(cc[0]*cc[0] + cc[0]);
                v0.y = r0.y + 0.1f*(cc[0]*cc[1] + cc[1]);
                v1.x = r1.x + 0.1f*(cc[2]*cc[2] + cc[2]);
                v1.y = r1.y + 0.1f*(cc[2]*cc[3] + cc[3]);
                *(float2*)&hOut[(size_t)row*512 + col] = v0;
                *(float2*)&hOut[(size_t)(row+8)*512 + col] = v1;
            }
        }
    }
}

// ----------------------------- host ---------------------------------------------
extern "C" void kernel_launch(void* const* d_in, const int* in_sizes, int n_in,
                              void* d_out, int out_size)
{
    const float* x      = (const float*)d_in[0];
    const float* h0     = (const float*)d_in[1];
    const float* theta  = (const float*)d_in[2];
    const float* damp_p = (const float*)d_in[3];
    const float* BWr    = (const float*)d_in[4];
    const float* BWi    = (const float*)d_in[5];
    const float* CWr    = (const float*)d_in[6];
    const float* CWi    = (const float*)d_in[7];
    const float* DWr    = (const float*)d_in[8];
    const float* DWi    = (const float*)d_in[9];
    const float* gW     = (const float*)d_in[10];
    const float* gb     = (const float*)d_in[11];
    const float* ng     = (const float*)d_in[12];
    const float* nb     = (const float*)d_in[13];
    const float* og     = (const float*)d_in[14];
    const float* ob     = (const float*)d_in[15];
    float* out = (float*)d_out;

    cudaFuncSetAttribute(mma_gemm, cudaFuncAttributeMaxDynamicSharedMemorySize, GEMM_SMEM);

    __nv_bfloat16 *a1, *a2, *w1, *w2;
    float *bx, *gt, *hbuf;
    cudaGetSymbolAddress((void**)&a1, g_A1);
    cudaGetSymbolAddress((void**)&a2, g_A2);
    cudaGetSymbolAddress((void**)&w1, g_W1);
    cudaGetSymbolAddress((void**)&w2, g_W2);
    cudaGetSymbolAddress((void**)&bx, g_Bx);
    cudaGetSymbolAddress((void**)&gt, g_gt);
    cudaGetSymbolAddress((void**)&hbuf, g_h);

    float* hfin = out + (size_t)Mc*Dc*2;

    {
        size_t n1 = (size_t)Lc*N1*K1;
        prep_w1<<<(unsigned)((n1+255)/256), 256>>>(BWr, BWi, gW);
        size_t n2 = (size_t)Lc*N2*K2;
        prep_w2<<<(unsigned)((n2+255)/256), 256>>>(CWr, CWi, DWr, DWi);
    }

    for (int l = 0; l < Lc; l++) {
        const float* src = (l == 0) ? x : hbuf;

        ln_kernel<<<Mc/8, 256>>>(src, ng + l*Dc, nb + l*Dc, 0, nullptr);

        // GEMM1: Bx + gates (A = A1 only; hallIters = 0)
        {
            dim3 g(N1/256, Mc/128);
            mma_gemm<<<g, 512, GEMM_SMEM>>>(a1, a1, w1 + (size_t)l*N1*K1, K1, 0, 0,
                                            bx, gt, gb + (size_t)l*SDc, nullptr, nullptr);
        }

        scan1<<<512, 256>>>(l, theta, damp_p);
        scan2<<<8, 256>>>(l, h0, hfin);
        scan3<<<512, 256>>>(l, theta, damp_p);

        // GEMM2: y = C*hall + D*xn; hall from A2 (48 iters), xn from A1
        {
            dim3 g(N2/256, Mc/128);
            mma_gemm<<<g, 512, GEMM_SMEM>>>(a1, a2, w2 + (size_t)l*N2*K2, K2, 48, 1,
                                            nullptr, nullptr, nullptr, src, hbuf);
        }
    }

    ln_kernel<<<Mc/8, 256>>>(hbuf, og, ob, 1, out);
}

// round 9
// speedup vs baseline: 1.3886x; 1.3886x over previous
#include <cuda_runtime.h>
#include <cuda_fp16.h>
#include <math.h>
#include <cstdint>

#define Lc   8
#define Bc   4
#define Sc   2048
#define Dc   256
#define SDc  512
#define Mc   (Bc*Sc)      // 8192

#define K1   1024         // W1 k-dim: [Whi|Whi] x 512
#define N1   1536         // 1024 (Bx interleaved) + 512 (gate)
#define K2   3072         // W2 k-dim: C [Whi|Whi]x1024 + D [Whi|Whi]x512
#define N2   512          // interleaved y pairs
#define KA1  1024         // A1 storage: [xn_hi 512 | xn_lo 512]
#define KA2  2048         // A2 storage: [hall_hi 1024 | hall_lo 1024]
#define NCH  64
#define CHLEN 32

// ----------------------------- device scratch --------------------------------
__device__ __half g_A1[(size_t)Mc*KA1];
__device__ __half g_A2[(size_t)Mc*KA2];
__device__ __half g_W1[(size_t)Lc*N1*K1];   // [l][n][k]
__device__ __half g_W2[(size_t)Lc*N2*K2];   // [l][n][k]
__device__ float g_Bx[(size_t)Mc*1024];     // interleaved (bxr,bxi)
__device__ float g_gt[(size_t)Mc*512];
__device__ float g_h [(size_t)Mc*512];      // interleaved activation
__device__ float g_carry[(size_t)NCH*Bc*SDc*4];
__device__ float g_hst  [(size_t)NCH*Bc*SDc*2];

// ----------------------------- helpers ----------------------------------------
__device__ __forceinline__ uint32_t s2u(const void* p){
    uint32_t a;
    asm("{ .reg .u64 t; cvta.to.shared.u64 t, %1; cvt.u32.u64 %0, t; }" : "=r"(a) : "l"(p));
    return a;
}
__device__ __forceinline__ void cpa16(uint32_t s, const void* g){
    asm volatile("cp.async.cg.shared.global [%0], [%1], 16;" :: "r"(s), "l"(g));
}
__device__ __forceinline__ uint32_t swz(uint32_t o){ return o ^ ((o >> 3) & 0x70); }

__device__ __forceinline__ void ldsm4(uint32_t* r, uint32_t addr){
    asm volatile("ldmatrix.sync.aligned.m8n8.x4.shared.b16 {%0,%1,%2,%3}, [%4];"
        : "=r"(r[0]), "=r"(r[1]), "=r"(r[2]), "=r"(r[3]) : "r"(addr));
}
__device__ __forceinline__ void mma16816(float* d, const uint32_t* a, const uint32_t* b){
    asm volatile("mma.sync.aligned.m16n8k16.row.col.f32.f16.f16.f32 "
        "{%0,%1,%2,%3}, {%4,%5,%6,%7}, {%8,%9}, {%0,%1,%2,%3};"
        : "+f"(d[0]), "+f"(d[1]), "+f"(d[2]), "+f"(d[3])
        : "r"(a[0]), "r"(a[1]), "r"(a[2]), "r"(a[3]), "r"(b[0]), "r"(b[1]));
}

// ----------------------------- weight prep ------------------------------------
// W1: [l][n][k], k in [0,1024): value depends on kk = k % 512 (duplicated blocks)
__global__ void prep_w1(const float* __restrict__ BWr, const float* __restrict__ BWi,
                        const float* __restrict__ gW)
{
    size_t i = (size_t)blockIdx.x * blockDim.x + threadIdx.x;
    if (i >= (size_t)Lc*N1*K1) return;
    int k = (int)(i % K1); size_t r = i / K1; int n = (int)(r % N1); int l = (int)(r / N1);
    int kk = k & 511;
    float v;
    if (n < 1024) {
        int j = n >> 1, p = n & 1;
        if (kk < 256) v = p ? BWi[((size_t)l*256+kk)*512+j] : BWr[((size_t)l*256+kk)*512+j];
        else { int kr = kk-256; v = p ? BWr[((size_t)l*256+kr)*512+j] : -BWi[((size_t)l*256+kr)*512+j]; }
    } else {
        v = gW[((size_t)l*512+kk)*512 + (n-1024)];
    }
    g_W1[i] = __float2half(v);
}

// W2: k<2048: C expand, kk = k % 1024; k>=2048: D expand, kk = (k-2048) % 512
__global__ void prep_w2(const float* __restrict__ CWr, const float* __restrict__ CWi,
                        const float* __restrict__ DWr, const float* __restrict__ DWi)
{
    size_t i = (size_t)blockIdx.x * blockDim.x + threadIdx.x;
    if (i >= (size_t)Lc*N2*K2) return;
    int k = (int)(i % K2); size_t r = i / K2; int n = (int)(r % N2); int l = (int)(r / N2);
    int j = n >> 1, p = n & 1;
    float v;
    if (k < 2048) {
        int kk = k & 1023;
        if (kk < 512) v = p ? CWi[((size_t)l*512+kk)*256+j] : CWr[((size_t)l*512+kk)*256+j];
        else { int ki = kk-512; v = p ? CWr[((size_t)l*512+ki)*256+j] : -CWi[((size_t)l*512+ki)*256+j]; }
    } else {
        int kk = (k - 2048) & 511;
        if (kk < 256) v = p ? DWi[((size_t)l*256+kk)*256+j] : DWr[((size_t)l*256+kk)*256+j];
        else { int kr = kk-256; v = p ? DWr[((size_t)l*256+kr)*256+j] : -DWi[((size_t)l*256+kr)*256+j]; }
    }
    g_W2[i] = __float2half(v);
}

// ----------------------------- LayerNorm (warp per row) ------------------------
__global__ void ln_kernel(const float* __restrict__ src,
                          const float* __restrict__ gw, const float* __restrict__ bw,
                          int final_mode, float* __restrict__ outInter)
{
    int warp = threadIdx.x >> 5, L = threadIdx.x & 31;
    int m = blockIdx.x * 8 + warp;
    const float4* row = (const float4*)(src + (size_t)m * 512);
    float4 v[4];
    float sr=0.f, si=0.f, qr=0.f, qi=0.f;
    #pragma unroll
    for (int j=0;j<4;j++){
        v[j] = row[L + 32*j];
        sr += v[j].x + v[j].z;  si += v[j].y + v[j].w;
        qr += v[j].x*v[j].x + v[j].z*v[j].z;
        qi += v[j].y*v[j].y + v[j].w*v[j].w;
    }
    #pragma unroll
    for (int o=16;o>0;o>>=1){
        sr += __shfl_xor_sync(0xffffffffu, sr, o);
        si += __shfl_xor_sync(0xffffffffu, si, o);
        qr += __shfl_xor_sync(0xffffffffu, qr, o);
        qi += __shfl_xor_sync(0xffffffffu, qi, o);
    }
    const float inv = 1.f/256.f;
    float mur = sr*inv, mui = si*inv;
    float isr = rsqrtf(qr*inv - mur*mur + 1e-5f);
    float isi = rsqrtf(qi*inv - mui*mui + 1e-5f);

    __half* a1 = g_A1 + (size_t)m * KA1;
    float* ointer = final_mode ? (outInter + (size_t)m*512) : nullptr;

    #pragma unroll
    for (int j=0;j<4;j++){
        int f = L + 32*j;
        float2 g2 = ((const float2*)gw)[f];
        float2 b2 = ((const float2*)bw)[f];
        float nr0 = (v[j].x - mur)*isr*g2.x + b2.x;
        float ni0 = (v[j].y - mui)*isi*g2.x + b2.x;
        float nr1 = (v[j].z - mur)*isr*g2.y + b2.y;
        float ni1 = (v[j].w - mui)*isi*g2.y + b2.y;
        if (final_mode) {
            float4 o4; o4.x=nr0; o4.y=ni0; o4.z=nr1; o4.w=ni1;
            ((float4*)ointer)[f] = o4;
        } else {
            int d0 = 2*f;
            __half2 rh = __floats2half2_rn(nr0, nr1);
            __half2 ih = __floats2half2_rn(ni0, ni1);
            __half2 rl = __floats2half2_rn(nr0 - __half2float(rh.x),
                                           nr1 - __half2float(rh.y));
            __half2 il = __floats2half2_rn(ni0 - __half2float(ih.x),
                                           ni1 - __half2float(ih.y));
            *(__half2*)(a1 + d0)       = rh;     // xn_hi real
            *(__half2*)(a1 + 256 + d0) = ih;     // xn_hi imag
            *(__half2*)(a1 + 512 + d0) = rl;     // xn_lo real
            *(__half2*)(a1 + 768 + d0) = il;     // xn_lo imag
        }
    }
}

// ----------------------------- scan (chunked) ----------------------------------
__global__ void scan1(int layer, const float* __restrict__ theta, const float* __restrict__ damp)
{
    int t = blockIdx.x*blockDim.x + threadIdx.x;   // 131072
    int sd = t & 511, ch = (t >> 9) & 63, b = t >> 15;
    float th = theta[layer*SDc+sd], dp = damp[layer*SDc+sd];
    float dm = 0.5f + 0.5f/(1.f+expf(-dp));
    float cd = cosf(th)*dm, sn = sinf(th)*dm;
    float Ar=1.f, Ai=0.f, Br=0.f, Bi=0.f;
    int base_row = b*Sc + ch*CHLEN;
    for (int s=0;s<CHLEN;s++){
        int row = base_row + s;
        float g = g_gt[(size_t)row*512+sd];
        float2 bx = *(const float2*)&g_Bx[(size_t)row*1024 + 2*sd];
        float og = 1.f - g;
        float ar = og*cd, ai = og*sn;
        float nAr = ar*Ar - ai*Ai, nAi = ar*Ai + ai*Ar;
        float nBr = ar*Br - ai*Bi + g*bx.x;
        float nBi = ar*Bi + ai*Br + g*bx.y;
        Ar=nAr; Ai=nAi; Br=nBr; Bi=nBi;
    }
    size_t o = ((size_t)ch*Bc*SDc + (size_t)b*SDc + sd)*4;
    float4 cc; cc.x=Ar; cc.y=Ai; cc.z=Br; cc.w=Bi;
    *(float4*)&g_carry[o] = cc;
}

__global__ void scan2(int layer, const float* __restrict__ h0, float* __restrict__ hfin)
{
    int t = blockIdx.x*blockDim.x + threadIdx.x;
    if (t >= Bc*SDc) return;
    int b = t / SDc, sd = t % SDc;
    size_t hidx = ((size_t)(layer*Bc+b)*SDc + sd)*2;
    float hr = h0[hidx], hi = h0[hidx+1];
    for (int ch = 0; ch < NCH; ch++){
        size_t o = (size_t)ch*Bc*SDc + t;
        g_hst[o*2] = hr; g_hst[o*2+1] = hi;
        float4 cc = *(const float4*)&g_carry[o*4];
        float nr = cc.x*hr - cc.y*hi + cc.z;
        float ni = cc.x*hi + cc.y*hr + cc.w;
        hr = nr; hi = ni;
    }
    hfin[hidx] = hr; hfin[hidx+1] = hi;
}

__global__ void scan3(int layer, const float* __restrict__ theta, const float* __restrict__ damp)
{
    int t = blockIdx.x*blockDim.x + threadIdx.x;
    int sd = t & 511, ch = (t >> 9) & 63, b = t >> 15;
    float th = theta[layer*SDc+sd], dp = damp[layer*SDc+sd];
    float dm = 0.5f + 0.5f/(1.f+expf(-dp));
    float cd = cosf(th)*dm, sn = sinf(th)*dm;
    size_t o = (size_t)ch*Bc*SDc + (size_t)b*SDc + sd;
    float hr = g_hst[o*2], hi = g_hst[o*2+1];
    int base_row = b*Sc + ch*CHLEN;
    for (int s=0;s<CHLEN;s++){
        int row = base_row + s;
        float g = g_gt[(size_t)row*512+sd];
        float2 bx = *(const float2*)&g_Bx[(size_t)row*1024 + 2*sd];
        float tr = hr*cd - hi*sn, ti = hr*sn + hi*cd;
        float og = 1.f - g;
        hr = fmaf(g, bx.x, og*tr);
        hi = fmaf(g, bx.y, og*ti);
        __half hh = __float2half(hr);
        __half hl = __float2half(hr - __half2float(hh));
        __half ih = __float2half(hi);
        __half il = __float2half(hi - __half2float(ih));
        __half* a2 = g_A2 + (size_t)row*KA2;
        a2[sd]=hh; a2[512+sd]=ih; a2[1024+sd]=hl; a2[1536+sd]=il;
    }
}

// ----------------------------- HMMA GEMM ---------------------------------------
// D[m][n] = sum_k A[m][k] * W[n][k]; fp16 2-term: A = [Ahi|Alo], W = [Whi|Whi].
// A k-index maps identity within region: ki < hallIters -> A2 (stride 2048),
// else A1 (stride 1024). 128x128 tile, 256 thr (2x4 warps, 64x32), ST=3, 2 CTA/SM.
// mode 0: n<1024 -> oBx; n>=1024 -> oGt = sigmoid(v + gb)
// mode 1: pairs (2j,2j+1)=(yr,yi): hOut = resid + 0.1*(yr*y + y)
#define ST 3
#define STAGE_BYTES 32768          // A 16KB + B 16KB
#define GEMM_SMEM (ST*STAGE_BYTES) // 96KB -> 2 CTAs/SM

__global__ void __launch_bounds__(256, 2)
mma_gemm(const __half* __restrict__ A1p, const __half* __restrict__ A2p,
         const __half* __restrict__ W, int KW, int hallIters, int mode,
         float* __restrict__ oBx, float* __restrict__ oGt, const float* __restrict__ gb,
         const float* __restrict__ resid, float* __restrict__ hOut)
{
    extern __shared__ char smem[];
    uint32_t sb = s2u(smem);
    int tid = threadIdx.x, wid = tid >> 5, L = tid & 31;
    int m0 = blockIdx.y * 128, n0 = blockIdx.x * 128;
    const int NK = KW >> 6;

    // ---- A chunks (4 x 16B per thread per stage) ----
    uint32_t rA[4], cA[4], soffA[4];
    #pragma unroll
    for (int i = 0; i < 4; i++) {
        int q = tid + i*256;              // 0..1023
        int r = q >> 3, c = q & 7;
        rA[i] = (uint32_t)(m0 + r);
        cA[i] = (uint32_t)(c * 8);
        soffA[i] = swz((uint32_t)(r*128 + c*16));
    }
    // ---- B chunks ----
    const __half* gBp[4]; uint32_t soffB[4];
    #pragma unroll
    for (int i = 0; i < 4; i++) {
        int q = (tid + (i+4)*256) & 1023;
        int r = q >> 3, c = q & 7;
        gBp[i] = W + (size_t)(n0 + r)*KW + c*8;
        soffB[i] = 16384u + swz((uint32_t)(r*128 + c*16));
    }

    // ---- ldmatrix lane addressing (SW128) ----
    int wm = wid >> 2, wn = wid & 3;
    int rowA0 = wm*64 + (L & 7) + ((L >> 3) & 1) * 8;
    uint32_t aBase = (uint32_t)rowA0 * 128; uint32_t aS = (uint32_t)(rowA0 & 7);
    uint32_t aC = (uint32_t)(L >> 4);
    int rowB0 = wn*32 + (L & 7) + ((L >> 4) & 1) * 8;
    uint32_t bBase = 16384u + (uint32_t)rowB0 * 128; uint32_t bS = (uint32_t)(rowB0 & 7);
    uint32_t bC = (uint32_t)((L >> 3) & 1);

    float c[4][4][4];
    #pragma unroll
    for (int i=0;i<4;i++)
        #pragma unroll
        for (int j=0;j<4;j++)
            #pragma unroll
            for (int e=0;e<4;e++) c[i][j][e] = 0.f;

    // stage loader: identity k-map within region
    auto load_stage = [&](int ki, uint32_t st){
        const __half* ab; int sh; uint32_t koff;
        if (ki < hallIters) { ab = A2p; sh = 11; koff = (uint32_t)(ki << 6); }
        else { ab = A1p; sh = 10; koff = (uint32_t)((ki - hallIters) << 6); }
        #pragma unroll
        for (int i = 0; i < 4; i++)
            cpa16(st + soffA[i], ab + ((rA[i] << sh) + koff + cA[i]));
        uint32_t kb = (uint32_t)(ki * 64);
        #pragma unroll
        for (int i = 0; i < 4; i++)
            cpa16(st + soffB[i], gBp[i] + kb);
    };

    // ---- prologue: load stages 0,1 ----
    #pragma unroll
    for (int s = 0; s < ST-1; s++) {
        if (s < NK) load_stage(s, sb + s*STAGE_BYTES);
        asm volatile("cp.async.commit_group;" ::: "memory");
    }

    for (int ki = 0; ki < NK; ki++) {
        asm volatile("cp.async.wait_group %0;" :: "n"(ST-2) : "memory");
        __syncthreads();

        uint32_t st = sb + (uint32_t)(ki % ST) * STAGE_BYTES;
        #pragma unroll
        for (int kk = 0; kk < 4; kk++) {
            uint32_t a[4][4], b[2][4];
            uint32_t ca = (uint32_t)(kk*2);
            #pragma unroll
            for (int mt = 0; mt < 4; mt++)
                ldsm4(a[mt], st + aBase + (uint32_t)mt*2048 + (((ca + aC) ^ aS) << 4));
            #pragma unroll
            for (int bt = 0; bt < 2; bt++)
                ldsm4(b[bt], st + bBase + (uint32_t)bt*2048 + (((ca + bC) ^ bS) << 4));
            #pragma unroll
            for (int mt = 0; mt < 4; mt++)
                #pragma unroll
                for (int nt = 0; nt < 4; nt++)
                    mma16816(c[mt][nt], a[mt], &b[nt>>1][(nt&1)*2]);
        }

        int ls = ki + ST - 1;
        if (ls < NK) load_stage(ls, sb + (uint32_t)(ls % ST) * STAGE_BYTES);
        asm volatile("cp.async.commit_group;" ::: "memory");
    }

    // ---- epilogue: direct float2 stores ----
    int lrow = L >> 2, lcol = (L & 3) * 2;
    int mRow = m0 + wm*64 + lrow;
    int nCol = n0 + wn*32 + lcol;
    #pragma unroll
    for (int mt = 0; mt < 4; mt++) {
        #pragma unroll
        for (int nt = 0; nt < 4; nt++) {
            int row = mRow + mt*16;
            int col = nCol + nt*8;
            float* cc = c[mt][nt];
            if (mode == 0) {
                if (col < 1024) {
                    float2 v0; v0.x = cc[0]; v0.y = cc[1];
                    float2 v1; v1.x = cc[2]; v1.y = cc[3];
                    *(float2*)&oBx[(size_t)row*1024 + col] = v0;
                    *(float2*)&oBx[(size_t)(row+8)*1024 + col] = v1;
                } else {
                    int gc = col - 1024;
                    float b0 = gb[gc], b1 = gb[gc+1];
                    float2 v0, v1;
                    v0.x = 1.f/(1.f+expf(-(cc[0]+b0)));
                    v0.y = 1.f/(1.f+expf(-(cc[1]+b1)));
                    v1.x = 1.f/(1.f+expf(-(cc[2]+b0)));
                    v1.y = 1.f/(1.f+expf(-(cc[3]+b1)));
                    *(float2*)&oGt[(size_t)row*512 + gc] = v0;
                    *(float2*)&oGt[(size_t)(row+8)*512 + gc] = v1;
                }
            } else {
                float2 r0 = *(const float2*)&resid[(size_t)row*512 + col];
                float2 r1 = *(const float2*)&resid[(size_t)(row+8)*512 + col];
                float2 v0, v1;
                v0.x = r0.x + 0.1f*(cc[0]*cc[0] + cc[0]);
                v0.y = r0.y + 0.1f*(cc[0]*cc[1] + cc[1]);
                v1.x = r1.x + 0.1f*(cc[2]*cc[2] + cc[2]);
                v1.y = r1.y + 0.1f*(cc[2]*cc[3] + cc[3]);
                *(float2*)&hOut[(size_t)row*512 + col] = v0;
                *(float2*)&hOut[(size_t)(row+8)*512 + col] = v1;
            }
        }
    }
}

// ----------------------------- host ---------------------------------------------
extern "C" void kernel_launch(void* const* d_in, const int* in_sizes, int n_in,
                              void* d_out, int out_size)
{
    const float* x      = (const float*)d_in[0];
    const float* h0     = (const float*)d_in[1];
    const float* theta  = (const float*)d_in[2];
    const float* damp_p = (const float*)d_in[3];
    const float* BWr    = (const float*)d_in[4];
    const float* BWi    = (const float*)d_in[5];
    const float* CWr    = (const float*)d_in[6];
    const float* CWi    = (const float*)d_in[7];
    const float* DWr    = (const float*)d_in[8];
    const float* DWi    = (const float*)d_in[9];
    const float* gW     = (const float*)d_in[10];
    const float* gb     = (const float*)d_in[11];
    const float* ng     = (const float*)d_in[12];
    const float* nb     = (const float*)d_in[13];
    const float* og     = (const float*)d_in[14];
    const float* ob     = (const float*)d_in[15];
    float* out = (float*)d_out;

    cudaFuncSetAttribute(mma_gemm, cudaFuncAttributeMaxDynamicSharedMemorySize, GEMM_SMEM);

    __half *a1, *a2, *w1, *w2;
    float *bx, *gt, *hbuf;
    cudaGetSymbolAddress((void**)&a1, g_A1);
    cudaGetSymbolAddress((void**)&a2, g_A2);
    cudaGetSymbolAddress((void**)&w1, g_W1);
    cudaGetSymbolAddress((void**)&w2, g_W2);
    cudaGetSymbolAddress((void**)&bx, g_Bx);
    cudaGetSymbolAddress((void**)&gt, g_gt);
    cudaGetSymbolAddress((void**)&hbuf, g_h);

    float* hfin = out + (size_t)Mc*Dc*2;

    {
        size_t n1 = (size_t)Lc*N1*K1;
        prep_w1<<<(unsigned)((n1+255)/256), 256>>>(BWr, BWi, gW);
        size_t n2 = (size_t)Lc*N2*K2;
        prep_w2<<<(unsigned)((n2+255)/256), 256>>>(CWr, CWi, DWr, DWi);
    }

    for (int l = 0; l < Lc; l++) {
        const float* src = (l == 0) ? x : hbuf;

        ln_kernel<<<Mc/8, 256>>>(src, ng + l*Dc, nb + l*Dc, 0, nullptr);

        // GEMM1: Bx + gates (A = A1 only; hallIters = 0; K = 1024)
        {
            dim3 g(N1/128, Mc/128);
            mma_gemm<<<g, 256, GEMM_SMEM>>>(a1, a1, w1 + (size_t)l*N1*K1, K1, 0, 0,
                                            bx, gt, gb + (size_t)l*SDc, nullptr, nullptr);
        }

        scan1<<<512, 256>>>(l, theta, damp_p);
        scan2<<<8, 256>>>(l, h0, hfin);
        scan3<<<512, 256>>>(l, theta, damp_p);

        // GEMM2: y = C*hall + D*xn; hall from A2 (32 iters), xn from A1; K = 3072
        {
            dim3 g(N2/128, Mc/128);
            mma_gemm<<<g, 256, GEMM_SMEM>>>(a1, a2, w2 + (size_t)l*N2*K2, K2, 32, 1,
                                            nullptr, nullptr, nullptr, src, hbuf);
        }
    }

    ln_kernel<<<Mc/8, 256>>>(hbuf, og, ob, 1, out);
}

// round 10
// speedup vs baseline: 2.1826x; 1.5718x over previous
#include <cuda_runtime.h>
#include <cuda_fp16.h>
#include <math.h>
#include <cstdint>

#define Lc   8
#define Bc   4
#define Sc   2048
#define Dc   256
#define SDc  512
#define Mc   (Bc*Sc)      // 8192

#define K1   512          // W1 k-dim (xn planes)
#define N1   1536         // 1024 (Bx interleaved) + 512 (gate)
#define K2   1536         // W2 k-dim: C x1024 + D x512
#define N2   512          // interleaved y pairs
#define KA1  512          // A1 storage: xn planes (fp16)
#define KA2  1024         // A2 storage: hall planes (fp16)
#define NCH  64
#define CHLEN 32

// ----------------------------- device scratch --------------------------------
__device__ __half g_A1[(size_t)Mc*KA1];
__device__ __half g_A2[(size_t)Mc*KA2];
__device__ __half g_W1[(size_t)Lc*N1*K1];   // [l][n][k]
__device__ __half g_W2[(size_t)Lc*N2*K2];   // [l][n][k]
__device__ float g_Bx[(size_t)Mc*1024];     // interleaved (bxr,bxi)
__device__ float g_gt[(size_t)Mc*512];
__device__ float g_h [(size_t)Mc*512];      // interleaved activation
__device__ float g_carry[(size_t)NCH*Bc*SDc*4];
__device__ float g_hst  [(size_t)NCH*Bc*SDc*2];

// ----------------------------- helpers ----------------------------------------
__device__ __forceinline__ uint32_t s2u(const void* p){
    uint32_t a;
    asm("{ .reg .u64 t; cvta.to.shared.u64 t, %1; cvt.u32.u64 %0, t; }" : "=r"(a) : "l"(p));
    return a;
}
__device__ __forceinline__ void cpa16(uint32_t s, const void* g){
    asm volatile("cp.async.cg.shared.global [%0], [%1], 16;" :: "r"(s), "l"(g));
}
__device__ __forceinline__ uint32_t swz(uint32_t o){ return o ^ ((o >> 3) & 0x70); }

__device__ __forceinline__ void ldsm4(uint32_t* r, uint32_t addr){
    asm volatile("ldmatrix.sync.aligned.m8n8.x4.shared.b16 {%0,%1,%2,%3}, [%4];"
        : "=r"(r[0]), "=r"(r[1]), "=r"(r[2]), "=r"(r[3]) : "r"(addr));
}
__device__ __forceinline__ void mma16816(float* d, const uint32_t* a, const uint32_t* b){
    asm volatile("mma.sync.aligned.m16n8k16.row.col.f32.f16.f16.f32 "
        "{%0,%1,%2,%3}, {%4,%5,%6,%7}, {%8,%9}, {%0,%1,%2,%3};"
        : "+f"(d[0]), "+f"(d[1]), "+f"(d[2]), "+f"(d[3])
        : "r"(a[0]), "r"(a[1]), "r"(a[2]), "r"(a[3]), "r"(b[0]), "r"(b[1]));
}

// ----------------------------- weight prep ------------------------------------
__global__ void prep_w1(const float* __restrict__ BWr, const float* __restrict__ BWi,
                        const float* __restrict__ gW)
{
    size_t i = (size_t)blockIdx.x * blockDim.x + threadIdx.x;
    if (i >= (size_t)Lc*N1*K1) return;
    int kk = (int)(i % K1); size_t r = i / K1; int n = (int)(r % N1); int l = (int)(r / N1);
    float v;
    if (n < 1024) {
        int j = n >> 1, p = n & 1;
        if (kk < 256) v = p ? BWi[((size_t)l*256+kk)*512+j] : BWr[((size_t)l*256+kk)*512+j];
        else { int kr = kk-256; v = p ? BWr[((size_t)l*256+kr)*512+j] : -BWi[((size_t)l*256+kr)*512+j]; }
    } else {
        v = gW[((size_t)l*512+kk)*512 + (n-1024)];
    }
    g_W1[i] = __float2half(v);
}

__global__ void prep_w2(const float* __restrict__ CWr, const float* __restrict__ CWi,
                        const float* __restrict__ DWr, const float* __restrict__ DWi)
{
    size_t i = (size_t)blockIdx.x * blockDim.x + threadIdx.x;
    if (i >= (size_t)Lc*N2*K2) return;
    int k = (int)(i % K2); size_t r = i / K2; int n = (int)(r % N2); int l = (int)(r / N2);
    int j = n >> 1, p = n & 1;
    float v;
    if (k < 1024) {
        int kk = k;
        if (kk < 512) v = p ? CWi[((size_t)l*512+kk)*256+j] : CWr[((size_t)l*512+kk)*256+j];
        else { int ki = kk-512; v = p ? CWr[((size_t)l*512+ki)*256+j] : -CWi[((size_t)l*512+ki)*256+j]; }
    } else {
        int kk = k - 1024;
        if (kk < 256) v = p ? DWi[((size_t)l*256+kk)*256+j] : DWr[((size_t)l*256+kk)*256+j];
        else { int kr = kk-256; v = p ? DWr[((size_t)l*256+kr)*256+j] : -DWi[((size_t)l*256+kr)*256+j]; }
    }
    g_W2[i] = __float2half(v);
}

// ----------------------------- LayerNorm (warp per row) ------------------------
__global__ void ln_kernel(const float* __restrict__ src,
                          const float* __restrict__ gw, const float* __restrict__ bw,
                          int final_mode, float* __restrict__ outInter)
{
    int warp = threadIdx.x >> 5, L = threadIdx.x & 31;
    int m = blockIdx.x * 8 + warp;
    const float4* row = (const float4*)(src + (size_t)m * 512);
    float4 v[4];
    float sr=0.f, si=0.f, qr=0.f, qi=0.f;
    #pragma unroll
    for (int j=0;j<4;j++){
        v[j] = row[L + 32*j];
        sr += v[j].x + v[j].z;  si += v[j].y + v[j].w;
        qr += v[j].x*v[j].x + v[j].z*v[j].z;
        qi += v[j].y*v[j].y + v[j].w*v[j].w;
    }
    #pragma unroll
    for (int o=16;o>0;o>>=1){
        sr += __shfl_xor_sync(0xffffffffu, sr, o);
        si += __shfl_xor_sync(0xffffffffu, si, o);
        qr += __shfl_xor_sync(0xffffffffu, qr, o);
        qi += __shfl_xor_sync(0xffffffffu, qi, o);
    }
    const float inv = 1.f/256.f;
    float mur = sr*inv, mui = si*inv;
    float isr = rsqrtf(qr*inv - mur*mur + 1e-5f);
    float isi = rsqrtf(qi*inv - mui*mui + 1e-5f);

    __half* a1 = g_A1 + (size_t)m * KA1;
    float* ointer = final_mode ? (outInter + (size_t)m*512) : nullptr;

    #pragma unroll
    for (int j=0;j<4;j++){
        int f = L + 32*j;
        float2 g2 = ((const float2*)gw)[f];
        float2 b2 = ((const float2*)bw)[f];
        float nr0 = (v[j].x - mur)*isr*g2.x + b2.x;
        float ni0 = (v[j].y - mui)*isi*g2.x + b2.x;
        float nr1 = (v[j].z - mur)*isr*g2.y + b2.y;
        float ni1 = (v[j].w - mui)*isi*g2.y + b2.y;
        if (final_mode) {
            float4 o4; o4.x=nr0; o4.y=ni0; o4.z=nr1; o4.w=ni1;
            ((float4*)ointer)[f] = o4;
        } else {
            int d0 = 2*f;
            *(__half2*)(a1 + d0)       = __floats2half2_rn(nr0, nr1);  // real plane
            *(__half2*)(a1 + 256 + d0) = __floats2half2_rn(ni0, ni1);  // imag plane
        }
    }
}

// ----------------------------- scan (chunked) ----------------------------------
__global__ void scan1(int layer, const float* __restrict__ theta, const float* __restrict__ damp)
{
    int t = blockIdx.x*blockDim.x + threadIdx.x;   // 131072
    int sd = t & 511, ch = (t >> 9) & 63, b = t >> 15;
    float th = theta[layer*SDc+sd], dp = damp[layer*SDc+sd];
    float dm = 0.5f + 0.5f/(1.f+expf(-dp));
    float cd = cosf(th)*dm, sn = sinf(th)*dm;
    float Ar=1.f, Ai=0.f, Br=0.f, Bi=0.f;
    int base_row = b*Sc + ch*CHLEN;
    for (int s=0;s<CHLEN;s++){
        int row = base_row + s;
        float g = g_gt[(size_t)row*512+sd];
        float2 bx = *(const float2*)&g_Bx[(size_t)row*1024 + 2*sd];
        float og = 1.f - g;
        float ar = og*cd, ai = og*sn;
        float nAr = ar*Ar - ai*Ai, nAi = ar*Ai + ai*Ar;
        float nBr = ar*Br - ai*Bi + g*bx.x;
        float nBi = ar*Bi + ai*Br + g*bx.y;
        Ar=nAr; Ai=nAi; Br=nBr; Bi=nBi;
    }
    size_t o = ((size_t)ch*Bc*SDc + (size_t)b*SDc + sd)*4;
    float4 cc; cc.x=Ar; cc.y=Ai; cc.z=Br; cc.w=Bi;
    *(float4*)&g_carry[o] = cc;
}

__global__ void scan2(int layer, const float* __restrict__ h0, float* __restrict__ hfin)
{
    int t = blockIdx.x*blockDim.x + threadIdx.x;
    if (t >= Bc*SDc) return;
    int b = t / SDc, sd = t % SDc;
    size_t hidx = ((size_t)(layer*Bc+b)*SDc + sd)*2;
    float hr = h0[hidx], hi = h0[hidx+1];
    for (int ch = 0; ch < NCH; ch++){
        size_t o = (size_t)ch*Bc*SDc + t;
        g_hst[o*2] = hr; g_hst[o*2+1] = hi;
        float4 cc = *(const float4*)&g_carry[o*4];
        float nr = cc.x*hr - cc.y*hi + cc.z;
        float ni = cc.x*hi + cc.y*hr + cc.w;
        hr = nr; hi = ni;
    }
    hfin[hidx] = hr; hfin[hidx+1] = hi;
}

__global__ void scan3(int layer, const float* __restrict__ theta, const float* __restrict__ damp)
{
    int t = blockIdx.x*blockDim.x + threadIdx.x;
    int sd = t & 511, ch = (t >> 9) & 63, b = t >> 15;
    float th = theta[layer*SDc+sd], dp = damp[layer*SDc+sd];
    float dm = 0.5f + 0.5f/(1.f+expf(-dp));
    float cd = cosf(th)*dm, sn = sinf(th)*dm;
    size_t o = (size_t)ch*Bc*SDc + (size_t)b*SDc + sd;
    float hr = g_hst[o*2], hi = g_hst[o*2+1];
    int base_row = b*Sc + ch*CHLEN;
    for (int s=0;s<CHLEN;s++){
        int row = base_row + s;
        float g = g_gt[(size_t)row*512+sd];
        float2 bx = *(const float2*)&g_Bx[(size_t)row*1024 + 2*sd];
        float tr = hr*cd - hi*sn, ti = hr*sn + hi*cd;
        float og = 1.f - g;
        hr = fmaf(g, bx.x, og*tr);
        hi = fmaf(g, bx.y, og*ti);
        __half* a2 = g_A2 + (size_t)row*KA2;
        a2[sd]     = __float2half(hr);
        a2[512+sd] = __float2half(hi);
    }
}

// ----------------------------- HMMA GEMM ---------------------------------------
// D[m][n] = sum_k A[m][k] * W[n][k]; fp16 1-term.
// A region: ki < hallIters -> A2 (stride 1024), else A1 (stride 512), identity k.
// 128x128 tile, 256 thr (2x4 warps, 64x32), ST=3, 2 CTA/SM.
// mode 0: n<1024 -> oBx; n>=1024 -> oGt = sigmoid(v + gb)
// mode 1: pairs (2j,2j+1)=(yr,yi): hOut = resid + 0.1*(yr*y + y)
#define ST 3
#define STAGE_BYTES 32768          // A 16KB + B 16KB
#define GEMM_SMEM (ST*STAGE_BYTES) // 96KB -> 2 CTAs/SM

__global__ void __launch_bounds__(256, 2)
mma_gemm(const __half* __restrict__ A1p, const __half* __restrict__ A2p,
         const __half* __restrict__ W, int KW, int hallIters, int mode,
         float* __restrict__ oBx, float* __restrict__ oGt, const float* __restrict__ gb,
         const float* __restrict__ resid, float* __restrict__ hOut)
{
    extern __shared__ char smem[];
    uint32_t sb = s2u(smem);
    int tid = threadIdx.x, wid = tid >> 5, L = tid & 31;
    int m0 = blockIdx.y * 128, n0 = blockIdx.x * 128;
    const int NK = KW >> 6;

    // ---- A chunks (4 x 16B per thread per stage) ----
    uint32_t rA[4], cA[4], soffA[4];
    #pragma unroll
    for (int i = 0; i < 4; i++) {
        int q = tid + i*256;              // 0..1023
        int r = q >> 3, c = q & 7;
        rA[i] = (uint32_t)(m0 + r);
        cA[i] = (uint32_t)(c * 8);
        soffA[i] = swz((uint32_t)(r*128 + c*16));
    }
    // ---- B chunks ----
    const __half* gBp[4]; uint32_t soffB[4];
    #pragma unroll
    for (int i = 0; i < 4; i++) {
        int q = (tid + (i+4)*256) & 1023;
        int r = q >> 3, c = q & 7;
        gBp[i] = W + (size_t)(n0 + r)*KW + c*8;
        soffB[i] = 16384u + swz((uint32_t)(r*128 + c*16));
    }

    // ---- ldmatrix lane addressing (SW128) ----
    int wm = wid >> 2, wn = wid & 3;
    int rowA0 = wm*64 + (L & 7) + ((L >> 3) & 1) * 8;
    uint32_t aBase = (uint32_t)rowA0 * 128; uint32_t aS = (uint32_t)(rowA0 & 7);
    uint32_t aC = (uint32_t)(L >> 4);
    int rowB0 = wn*32 + (L & 7) + ((L >> 4) & 1) * 8;
    uint32_t bBase = 16384u + (uint32_t)rowB0 * 128; uint32_t bS = (uint32_t)(rowB0 & 7);
    uint32_t bC = (uint32_t)((L >> 3) & 1);

    float c[4][4][4];
    #pragma unroll
    for (int i=0;i<4;i++)
        #pragma unroll
        for (int j=0;j<4;j++)
            #pragma unroll
            for (int e=0;e<4;e++) c[i][j][e] = 0.f;

    // stage loader: identity k-map within region
    auto load_stage = [&](int ki, uint32_t st){
        const __half* ab; int sh; uint32_t koff;
        if (ki < hallIters) { ab = A2p; sh = 10; koff = (uint32_t)(ki << 6); }
        else { ab = A1p; sh = 9; koff = (uint32_t)((ki - hallIters) << 6); }
        #pragma unroll
        for (int i = 0; i < 4; i++)
            cpa16(st + soffA[i], ab + ((rA[i] << sh) + koff + cA[i]));
        uint32_t kb = (uint32_t)(ki * 64);
        #pragma unroll
        for (int i = 0; i < 4; i++)
            cpa16(st + soffB[i], gBp[i] + kb);
    };

    // ---- prologue: load stages 0,1 ----
    #pragma unroll
    for (int s = 0; s < ST-1; s++) {
        if (s < NK) load_stage(s, sb + s*STAGE_BYTES);
        asm volatile("cp.async.commit_group;" ::: "memory");
    }

    for (int ki = 0; ki < NK; ki++) {
        asm volatile("cp.async.wait_group %0;" :: "n"(ST-2) : "memory");
        __syncthreads();

        uint32_t st = sb + (uint32_t)(ki % ST) * STAGE_BYTES;
        #pragma unroll
        for (int kk = 0; kk < 4; kk++) {
            uint32_t a[4][4], b[2][4];
            uint32_t ca = (uint32_t)(kk*2);
            #pragma unroll
            for (int mt = 0; mt < 4; mt++)
                ldsm4(a[mt], st + aBase + (uint32_t)mt*2048 + (((ca + aC) ^ aS) << 4));
            #pragma unroll
            for (int bt = 0; bt < 2; bt++)
                ldsm4(b[bt], st + bBase + (uint32_t)bt*2048 + (((ca + bC) ^ bS) << 4));
            #pragma unroll
            for (int mt = 0; mt < 4; mt++)
                #pragma unroll
                for (int nt = 0; nt < 4; nt++)
                    mma16816(c[mt][nt], a[mt], &b[nt>>1][(nt&1)*2]);
        }

        int ls = ki + ST - 1;
        if (ls < NK) load_stage(ls, sb + (uint32_t)(ls % ST) * STAGE_BYTES);
        asm volatile("cp.async.commit_group;" ::: "memory");
    }

    // ---- epilogue: direct float2 stores ----
    int lrow = L >> 2, lcol = (L & 3) * 2;
    int mRow = m0 + wm*64 + lrow;
    int nCol = n0 + wn*32 + lcol;
    #pragma unroll
    for (int mt = 0; mt < 4; mt++) {
        #pragma unroll
        for (int nt = 0; nt < 4; nt++) {
            int row = mRow + mt*16;
            int col = nCol + nt*8;
            float* cc = c[mt][nt];
            if (mode == 0) {
                if (col < 1024) {
                    float2 v0; v0.x = cc[0]; v0.y = cc[1];
                    float2 v1; v1.x = cc[2]; v1.y = cc[3];
                    *(float2*)&oBx[(size_t)row*1024 + col] = v0;
                    *(float2*)&oBx[(size_t)(row+8)*1024 + col] = v1;
                } else {
                    int gc = col - 1024;
                    float b0 = gb[gc], b1 = gb[gc+1];
                    float2 v0, v1;
                    v0.x = 1.f/(1.f+expf(-(cc[0]+b0)));
                    v0.y = 1.f/(1.f+expf(-(cc[1]+b1)));
                    v1.x = 1.f/(1.f+expf(-(cc[2]+b0)));
                    v1.y = 1.f/(1.f+expf(-(cc[3]+b1)));
                    *(float2*)&oGt[(size_t)row*512 + gc] = v0;
                    *(float2*)&oGt[(size_t)(row+8)*512 + gc] = v1;
                }
            } else {
                float2 r0 = *(const float2*)&resid[(size_t)row*512 + col];
                float2 r1 = *(const float2*)&resid[(size_t)(row+8)*512 + col];
                float2 v0, v1;
                v0.x = r0.x + 0.1f*(cc[0]*cc[0] + cc[0]);
                v0.y = r0.y + 0.1f*(cc[0]*cc[1] + cc[1]);
                v1.x = r1.x + 0.1f*(cc[2]*cc[2] + cc[2]);
                v1.y = r1.y + 0.1f*(cc[2]*cc[3] + cc[3]);
                *(float2*)&hOut[(size_t)row*512 + col] = v0;
                *(float2*)&hOut[(size_t)(row+8)*512 + col] = v1;
            }
        }
    }
}

// ----------------------------- host ---------------------------------------------
extern "C" void kernel_launch(void* const* d_in, const int* in_sizes, int n_in,
                              void* d_out, int out_size)
{
    const float* x      = (const float*)d_in[0];
    const float* h0     = (const float*)d_in[1];
    const float* theta  = (const float*)d_in[2];
    const float* damp_p = (const float*)d_in[3];
    const float* BWr    = (const float*)d_in[4];
    const float* BWi    = (const float*)d_in[5];
    const float* CWr    = (const float*)d_in[6];
    const float* CWi    = (const float*)d_in[7];
    const float* DWr    = (const float*)d_in[8];
    const float* DWi    = (const float*)d_in[9];
    const float* gW     = (const float*)d_in[10];
    const float* gb     = (const float*)d_in[11];
    const float* ng     = (const float*)d_in[12];
    const float* nb     = (const float*)d_in[13];
    const float* og     = (const float*)d_in[14];
    const float* ob     = (const float*)d_in[15];
    float* out = (float*)d_out;

    cudaFuncSetAttribute(mma_gemm, cudaFuncAttributeMaxDynamicSharedMemorySize, GEMM_SMEM);

    __half *a1, *a2, *w1, *w2;
    float *bx, *gt, *hbuf;
    cudaGetSymbolAddress((void**)&a1, g_A1);
    cudaGetSymbolAddress((void**)&a2, g_A2);
    cudaGetSymbolAddress((void**)&w1, g_W1);
    cudaGetSymbolAddress((void**)&w2, g_W2);
    cudaGetSymbolAddress((void**)&bx, g_Bx);
    cudaGetSymbolAddress((void**)&gt, g_gt);
    cudaGetSymbolAddress((void**)&hbuf, g_h);

    float* hfin = out + (size_t)Mc*Dc*2;

    {
        size_t n1 = (size_t)Lc*N1*K1;
        prep_w1<<<(unsigned)((n1+255)/256), 256>>>(BWr, BWi, gW);
        size_t n2 = (size_t)Lc*N2*K2;
        prep_w2<<<(unsigned)((n2+255)/256), 256>>>(CWr, CWi, DWr, DWi);
    }

    for (int l = 0; l < Lc; l++) {
        const float* src = (l == 0) ? x : hbuf;

        ln_kernel<<<Mc/8, 256>>>(src, ng + l*Dc, nb + l*Dc, 0, nullptr);

        // GEMM1: Bx + gates (A = A1 only; hallIters = 0; K = 512)
        {
            dim3 g(N1/128, Mc/128);
            mma_gemm<<<g, 256, GEMM_SMEM>>>(a1, a1, w1 + (size_t)l*N1*K1, K1, 0, 0,
                                            bx, gt, gb + (size_t)l*SDc, nullptr, nullptr);
        }

        scan1<<<512, 256>>>(l, theta, damp_p);
        scan2<<<8, 256>>>(l, h0, hfin);
        scan3<<<512, 256>>>(l, theta, damp_p);

        // GEMM2: y = C*hall + D*xn; hall from A2 (16 iters), xn from A1; K = 1536
        {
            dim3 g(N2/128, Mc/128);
            mma_gemm<<<g, 256, GEMM_SMEM>>>(a1, a2, w2 + (size_t)l*N2*K2, K2, 16, 1,
                                            nullptr, nullptr, nullptr, src, hbuf);
        }
    }

    ln_kernel<<<Mc/8, 256>>>(hbuf, og, ob, 1, out);
}

// round 11
// speedup vs baseline: 2.3781x; 1.0896x over previous
#include <cuda_runtime.h>
#include <cuda_fp16.h>
#include <math.h>
#include <cstdint>

#define Lc   8
#define Bc   4
#define Sc   2048
#define Dc   256
#define SDc  512
#define Mc   (Bc*Sc)      // 8192

#define K1   512          // W1 k-dim (xn planes)
#define N1   1536         // 1024 (Bx interleaved) + 512 (gate)
#define K2   1536         // W2 k-dim: C x1024 + D x512
#define N2   512          // interleaved y pairs
#define KA1  512          // A1 storage: xn planes (fp16)
#define KA2  1024         // A2 storage: hall planes (fp16)

// ----------------------------- device scratch --------------------------------
__device__ __half g_A1[(size_t)Mc*KA1];
__device__ __half g_A2[(size_t)Mc*KA2];
__device__ __half g_W1[(size_t)Lc*N1*K1];   // [l][n][k]
__device__ __half g_W2[(size_t)Lc*N2*K2];   // [l][n][k]
__device__ float g_Bx[(size_t)Mc*1024];     // interleaved (bxr,bxi)
__device__ float g_gt[(size_t)Mc*512];
__device__ float g_h [(size_t)Mc*512];      // interleaved activation

// ----------------------------- helpers ----------------------------------------
__device__ __forceinline__ uint32_t s2u(const void* p){
    uint32_t a;
    asm("{ .reg .u64 t; cvta.to.shared.u64 t, %1; cvt.u32.u64 %0, t; }" : "=r"(a) : "l"(p));
    return a;
}
__device__ __forceinline__ void cpa16(uint32_t s, const void* g){
    asm volatile("cp.async.cg.shared.global [%0], [%1], 16;" :: "r"(s), "l"(g));
}
__device__ __forceinline__ uint32_t swz(uint32_t o){ return o ^ ((o >> 3) & 0x70); }

__device__ __forceinline__ void ldsm4(uint32_t* r, uint32_t addr){
    asm volatile("ldmatrix.sync.aligned.m8n8.x4.shared.b16 {%0,%1,%2,%3}, [%4];"
        : "=r"(r[0]), "=r"(r[1]), "=r"(r[2]), "=r"(r[3]) : "r"(addr));
}
__device__ __forceinline__ void mma16816(float* d, const uint32_t* a, const uint32_t* b){
    asm volatile("mma.sync.aligned.m16n8k16.row.col.f32.f16.f16.f32 "
        "{%0,%1,%2,%3}, {%4,%5,%6,%7}, {%8,%9}, {%0,%1,%2,%3};"
        : "+f"(d[0]), "+f"(d[1]), "+f"(d[2]), "+f"(d[3])
        : "r"(a[0]), "r"(a[1]), "r"(a[2]), "r"(a[3]), "r"(b[0]), "r"(b[1]));
}

// ----------------------------- weight prep ------------------------------------
__global__ void prep_w1(const float* __restrict__ BWr, const float* __restrict__ BWi,
                        const float* __restrict__ gW)
{
    size_t i = (size_t)blockIdx.x * blockDim.x + threadIdx.x;
    if (i >= (size_t)Lc*N1*K1) return;
    int kk = (int)(i % K1); size_t r = i / K1; int n = (int)(r % N1); int l = (int)(r / N1);
    float v;
    if (n < 1024) {
        int j = n >> 1, p = n & 1;
        if (kk < 256) v = p ? BWi[((size_t)l*256+kk)*512+j] : BWr[((size_t)l*256+kk)*512+j];
        else { int kr = kk-256; v = p ? BWr[((size_t)l*256+kr)*512+j] : -BWi[((size_t)l*256+kr)*512+j]; }
    } else {
        v = gW[((size_t)l*512+kk)*512 + (n-1024)];
    }
    g_W1[i] = __float2half(v);
}

__global__ void prep_w2(const float* __restrict__ CWr, const float* __restrict__ CWi,
                        const float* __restrict__ DWr, const float* __restrict__ DWi)
{
    size_t i = (size_t)blockIdx.x * blockDim.x + threadIdx.x;
    if (i >= (size_t)Lc*N2*K2) return;
    int k = (int)(i % K2); size_t r = i / K2; int n = (int)(r % N2); int l = (int)(r / N2);
    int j = n >> 1, p = n & 1;
    float v;
    if (k < 1024) {
        int kk = k;
        if (kk < 512) v = p ? CWi[((size_t)l*512+kk)*256+j] : CWr[((size_t)l*512+kk)*256+j];
        else { int ki = kk-512; v = p ? CWr[((size_t)l*512+ki)*256+j] : -CWi[((size_t)l*512+ki)*256+j]; }
    } else {
        int kk = k - 1024;
        if (kk < 256) v = p ? DWi[((size_t)l*256+kk)*256+j] : DWr[((size_t)l*256+kk)*256+j];
        else { int kr = kk-256; v = p ? DWr[((size_t)l*256+kr)*256+j] : -DWi[((size_t)l*256+kr)*256+j]; }
    }
    g_W2[i] = __float2half(v);
}

// ----------------------------- LayerNorm (warp per row) ------------------------
__global__ void ln_kernel(const float* __restrict__ src,
                          const float* __restrict__ gw, const float* __restrict__ bw,
                          int final_mode, float* __restrict__ outInter)
{
    int warp = threadIdx.x >> 5, L = threadIdx.x & 31;
    int m = blockIdx.x * 8 + warp;
    const float4* row = (const float4*)(src + (size_t)m * 512);
    float4 v[4];
    float sr=0.f, si=0.f, qr=0.f, qi=0.f;
    #pragma unroll
    for (int j=0;j<4;j++){
        v[j] = row[L + 32*j];
        sr += v[j].x + v[j].z;  si += v[j].y + v[j].w;
        qr += v[j].x*v[j].x + v[j].z*v[j].z;
        qi += v[j].y*v[j].y + v[j].w*v[j].w;
    }
    #pragma unroll
    for (int o=16;o>0;o>>=1){
        sr += __shfl_xor_sync(0xffffffffu, sr, o);
        si += __shfl_xor_sync(0xffffffffu, si, o);
        qr += __shfl_xor_sync(0xffffffffu, qr, o);
        qi += __shfl_xor_sync(0xffffffffu, qi, o);
    }
    const float inv = 1.f/256.f;
    float mur = sr*inv, mui = si*inv;
    float isr = rsqrtf(qr*inv - mur*mur + 1e-5f);
    float isi = rsqrtf(qi*inv - mui*mui + 1e-5f);

    __half* a1 = g_A1 + (size_t)m * KA1;
    float* ointer = final_mode ? (outInter + (size_t)m*512) : nullptr;

    #pragma unroll
    for (int j=0;j<4;j++){
        int f = L + 32*j;
        float2 g2 = ((const float2*)gw)[f];
        float2 b2 = ((const float2*)bw)[f];
        float nr0 = (v[j].x - mur)*isr*g2.x + b2.x;
        float ni0 = (v[j].y - mui)*isi*g2.x + b2.x;
        float nr1 = (v[j].z - mur)*isr*g2.y + b2.y;
        float ni1 = (v[j].w - mui)*isi*g2.y + b2.y;
        if (final_mode) {
            float4 o4; o4.x=nr0; o4.y=ni0; o4.z=nr1; o4.w=ni1;
            ((float4*)ointer)[f] = o4;
        } else {
            int d0 = 2*f;
            *(__half2*)(a1 + d0)       = __floats2half2_rn(nr0, nr1);  // real plane
            *(__half2*)(a1 + 256 + d0) = __floats2half2_rn(ni0, ni1);  // imag plane
        }
    }
}

// ----------------------------- fused scan ---------------------------------------
// Block = 1024 threads = 32 warps. Block handles (b, 32-sd tile), warp w = chunk w
// (rows [b*2048 + w*64, +64)), lane = sd within tile (coalesced).
// Phase1: per-thread 64-step chunk scan -> (A,B) carry to smem.
// Phase2: warp 0 serial prefix over 32 chunks per sd; writes hfin.
// Phase3: rescan chunk with correct start state; write A2 fp16 planes.
__global__ void __launch_bounds__(1024, 1)
scan_fused(int layer, const float* __restrict__ theta, const float* __restrict__ damp,
           const float* __restrict__ h0, float* __restrict__ hfin)
{
    __shared__ float4 scarry[32][33];
    __shared__ float2 sstart[32][33];
    int tid = threadIdx.x;
    int w = tid >> 5, lane = tid & 31;        // w = chunk, lane = sd_local
    int b = blockIdx.x >> 4, sdt = blockIdx.x & 15;
    int sd = sdt*32 + lane;

    float th = theta[layer*SDc+sd], dp = damp[layer*SDc+sd];
    float dm = 0.5f + 0.5f/(1.f+expf(-dp));
    float cd = cosf(th)*dm, sn = sinf(th)*dm;

    int base_row = b*Sc + w*64;

    // Phase 1: chunk carry
    float Ar=1.f, Ai=0.f, Br=0.f, Bi=0.f;
    #pragma unroll 4
    for (int s=0;s<64;s++){
        int row = base_row + s;
        float g = g_gt[(size_t)row*512+sd];
        float2 bx = *(const float2*)&g_Bx[(size_t)row*1024 + 2*sd];
        float og = 1.f - g;
        float ar = og*cd, ai = og*sn;
        float nAr = ar*Ar - ai*Ai, nAi = ar*Ai + ai*Ar;
        float nBr = ar*Br - ai*Bi + g*bx.x;
        float nBi = ar*Bi + ai*Br + g*bx.y;
        Ar=nAr; Ai=nAi; Br=nBr; Bi=nBi;
    }
    float4 cv; cv.x=Ar; cv.y=Ai; cv.z=Br; cv.w=Bi;
    scarry[w][lane] = cv;
    __syncthreads();

    // Phase 2: prefix over chunks (warp 0; lane owns its sd)
    if (w == 0) {
        size_t hidx = ((size_t)(layer*Bc+b)*SDc + sd)*2;
        float hr = h0[hidx], hi = h0[hidx+1];
        #pragma unroll
        for (int c=0;c<32;c++){
            float2 s2; s2.x=hr; s2.y=hi;
            sstart[c][lane] = s2;
            float4 cc = scarry[c][lane];
            float nr = cc.x*hr - cc.y*hi + cc.z;
            float ni = cc.x*hi + cc.y*hr + cc.w;
            hr=nr; hi=ni;
        }
        hfin[hidx]   = hr;
        hfin[hidx+1] = hi;
    }
    __syncthreads();

    // Phase 3: rescan with start state, emit fp16 planes
    float2 st0 = sstart[w][lane];
    float hr = st0.x, hi = st0.y;
    #pragma unroll 4
    for (int s=0;s<64;s++){
        int row = base_row + s;
        float g = g_gt[(size_t)row*512+sd];
        float2 bx = *(const float2*)&g_Bx[(size_t)row*1024 + 2*sd];
        float tr = hr*cd - hi*sn, ti = hr*sn + hi*cd;
        float og = 1.f - g;
        hr = fmaf(g, bx.x, og*tr);
        hi = fmaf(g, bx.y, og*ti);
        __half* a2 = g_A2 + (size_t)row*KA2;
        a2[sd]     = __float2half(hr);
        a2[512+sd] = __float2half(hi);
    }
}

// ----------------------------- HMMA GEMM ---------------------------------------
// D[m][n] = sum_k A[m][k] * W[n][k]; fp16 1-term.
// A region: ki < hallIters -> A2 (stride 1024), else A1 (stride 512), identity k.
// 128x128 tile, 256 thr (2x4 warps, 64x32), ST=3, 2 CTA/SM.
// mode 0: n<1024 -> oBx; n>=1024 -> oGt = sigmoid(v + gb)
// mode 1: pairs (2j,2j+1)=(yr,yi): hOut = resid + 0.1*(yr*y + y)
#define ST 3
#define STAGE_BYTES 32768          // A 16KB + B 16KB
#define GEMM_SMEM (ST*STAGE_BYTES) // 96KB -> 2 CTAs/SM

__global__ void __launch_bounds__(256, 2)
mma_gemm(const __half* __restrict__ A1p, const __half* __restrict__ A2p,
         const __half* __restrict__ W, int KW, int hallIters, int mode,
         float* __restrict__ oBx, float* __restrict__ oGt, const float* __restrict__ gb,
         const float* __restrict__ resid, float* __restrict__ hOut)
{
    extern __shared__ char smem[];
    uint32_t sb = s2u(smem);
    int tid = threadIdx.x, wid = tid >> 5, L = tid & 31;
    int m0 = blockIdx.y * 128, n0 = blockIdx.x * 128;
    const int NK = KW >> 6;

    // ---- A chunks (4 x 16B per thread per stage) ----
    uint32_t rA[4], cA[4], soffA[4];
    #pragma unroll
    for (int i = 0; i < 4; i++) {
        int q = tid + i*256;              // 0..1023
        int r = q >> 3, c = q & 7;
        rA[i] = (uint32_t)(m0 + r);
        cA[i] = (uint32_t)(c * 8);
        soffA[i] = swz((uint32_t)(r*128 + c*16));
    }
    // ---- B chunks ----
    const __half* gBp[4]; uint32_t soffB[4];
    #pragma unroll
    for (int i = 0; i < 4; i++) {
        int q = (tid + (i+4)*256) & 1023;
        int r = q >> 3, c = q & 7;
        gBp[i] = W + (size_t)(n0 + r)*KW + c*8;
        soffB[i] = 16384u + swz((uint32_t)(r*128 + c*16));
    }

    // ---- ldmatrix lane addressing (SW128) ----
    int wm = wid >> 2, wn = wid & 3;
    int rowA0 = wm*64 + (L & 7) + ((L >> 3) & 1) * 8;
    uint32_t aBase = (uint32_t)rowA0 * 128; uint32_t aS = (uint32_t)(rowA0 & 7);
    uint32_t aC = (uint32_t)(L >> 4);
    int rowB0 = wn*32 + (L & 7) + ((L >> 4) & 1) * 8;
    uint32_t bBase = 16384u + (uint32_t)rowB0 * 128; uint32_t bS = (uint32_t)(rowB0 & 7);
    uint32_t bC = (uint32_t)((L >> 3) & 1);

    float c[4][4][4];
    #pragma unroll
    for (int i=0;i<4;i++)
        #pragma unroll
        for (int j=0;j<4;j++)
            #pragma unroll
            for (int e=0;e<4;e++) c[i][j][e] = 0.f;

    // stage loader: identity k-map within region
    auto load_stage = [&](int ki, uint32_t st){
        const __half* ab; int sh; uint32_t koff;
        if (ki < hallIters) { ab = A2p; sh = 10; koff = (uint32_t)(ki << 6); }
        else { ab = A1p; sh = 9; koff = (uint32_t)((ki - hallIters) << 6); }
        #pragma unroll
        for (int i = 0; i < 4; i++)
            cpa16(st + soffA[i], ab + ((rA[i] << sh) + koff + cA[i]));
        uint32_t kb = (uint32_t)(ki * 64);
        #pragma unroll
        for (int i = 0; i < 4; i++)
            cpa16(st + soffB[i], gBp[i] + kb);
    };

    // ---- prologue: load stages 0,1 ----
    #pragma unroll
    for (int s = 0; s < ST-1; s++) {
        if (s < NK) load_stage(s, sb + s*STAGE_BYTES);
        asm volatile("cp.async.commit_group;" ::: "memory");
    }

    for (int ki = 0; ki < NK; ki++) {
        asm volatile("cp.async.wait_group %0;" :: "n"(ST-2) : "memory");
        __syncthreads();

        uint32_t st = sb + (uint32_t)(ki % ST) * STAGE_BYTES;
        #pragma unroll
        for (int kk = 0; kk < 4; kk++) {
            uint32_t a[4][4], b[2][4];
            uint32_t ca = (uint32_t)(kk*2);
            #pragma unroll
            for (int mt = 0; mt < 4; mt++)
                ldsm4(a[mt], st + aBase + (uint32_t)mt*2048 + (((ca + aC) ^ aS) << 4));
            #pragma unroll
            for (int bt = 0; bt < 2; bt++)
                ldsm4(b[bt], st + bBase + (uint32_t)bt*2048 + (((ca + bC) ^ bS) << 4));
            #pragma unroll
            for (int mt = 0; mt < 4; mt++)
                #pragma unroll
                for (int nt = 0; nt < 4; nt++)
                    mma16816(c[mt][nt], a[mt], &b[nt>>1][(nt&1)*2]);
        }

        int ls = ki + ST - 1;
        if (ls < NK) load_stage(ls, sb + (uint32_t)(ls % ST) * STAGE_BYTES);
        asm volatile("cp.async.commit_group;" ::: "memory");
    }

    // ---- epilogue: direct float2 stores ----
    int lrow = L >> 2, lcol = (L & 3) * 2;
    int mRow = m0 + wm*64 + lrow;
    int nCol = n0 + wn*32 + lcol;
    #pragma unroll
    for (int mt = 0; mt < 4; mt++) {
        #pragma unroll
        for (int nt = 0; nt < 4; nt++) {
            int row = mRow + mt*16;
            int col = nCol + nt*8;
            float* cc = c[mt][nt];
            if (mode == 0) {
                if (col < 1024) {
                    float2 v0; v0.x = cc[0]; v0.y = cc[1];
                    float2 v1; v1.x = cc[2]; v1.y = cc[3];
                    *(float2*)&oBx[(size_t)row*1024 + col] = v0;
                    *(float2*)&oBx[(size_t)(row+8)*1024 + col] = v1;
                } else {
                    int gc = col - 1024;
                    float b0 = gb[gc], b1 = gb[gc+1];
                    float2 v0, v1;
                    v0.x = 1.f/(1.f+expf(-(cc[0]+b0)));
                    v0.y = 1.f/(1.f+expf(-(cc[1]+b1)));
                    v1.x = 1.f/(1.f+expf(-(cc[2]+b0)));
                    v1.y = 1.f/(1.f+expf(-(cc[3]+b1)));
                    *(float2*)&oGt[(size_t)row*512 + gc] = v0;
                    *(float2*)&oGt[(size_t)(row+8)*512 + gc] = v1;
                }
            } else {
                float2 r0 = *(const float2*)&resid[(size_t)row*512 + col];
                float2 r1 = *(const float2*)&resid[(size_t)(row+8)*512 + col];
                float2 v0, v1;
                v0.x = r0.x + 0.1f*(cc[0]*cc[0] + cc[0]);
                v0.y = r0.y + 0.1f*(cc[0]*cc[1] + cc[1]);
                v1.x = r1.x + 0.1f*(cc[2]*cc[2] + cc[2]);
                v1.y = r1.y + 0.1f*(cc[2]*cc[3] + cc[3]);
                *(float2*)&hOut[(size_t)row*512 + col] = v0;
                *(float2*)&hOut[(size_t)(row+8)*512 + col] = v1;
            }
        }
    }
}

// ----------------------------- host ---------------------------------------------
extern "C" void kernel_launch(void* const* d_in, const int* in_sizes, int n_in,
                              void* d_out, int out_size)
{
    const float* x      = (const float*)d_in[0];
    const float* h0     = (const float*)d_in[1];
    const float* theta  = (const float*)d_in[2];
    const float* damp_p = (const float*)d_in[3];
    const float* BWr    = (const float*)d_in[4];
    const float* BWi    = (const float*)d_in[5];
    const float* CWr    = (const float*)d_in[6];
    const float* CWi    = (const float*)d_in[7];
    const float* DWr    = (const float*)d_in[8];
    const float* DWi    = (const float*)d_in[9];
    const float* gW     = (const float*)d_in[10];
    const float* gb     = (const float*)d_in[11];
    const float* ng     = (const float*)d_in[12];
    const float* nb     = (const float*)d_in[13];
    const float* og     = (const float*)d_in[14];
    const float* ob     = (const float*)d_in[15];
    float* out = (float*)d_out;

    cudaFuncSetAttribute(mma_gemm, cudaFuncAttributeMaxDynamicSharedMemorySize, GEMM_SMEM);

    __half *a1, *a2, *w1, *w2;
    float *bx, *gt, *hbuf;
    cudaGetSymbolAddress((void**)&a1, g_A1);
    cudaGetSymbolAddress((void**)&a2, g_A2);
    cudaGetSymbolAddress((void**)&w1, g_W1);
    cudaGetSymbolAddress((void**)&w2, g_W2);
    cudaGetSymbolAddress((void**)&bx, g_Bx);
    cudaGetSymbolAddress((void**)&gt, g_gt);
    cudaGetSymbolAddress((void**)&hbuf, g_h);

    float* hfin = out + (size_t)Mc*Dc*2;

    {
        size_t n1 = (size_t)Lc*N1*K1;
        prep_w1<<<(unsigned)((n1+255)/256), 256>>>(BWr, BWi, gW);
        size_t n2 = (size_t)Lc*N2*K2;
        prep_w2<<<(unsigned)((n2+255)/256), 256>>>(CWr, CWi, DWr, DWi);
    }

    for (int l = 0; l < Lc; l++) {
        const float* src = (l == 0) ? x : hbuf;

        ln_kernel<<<Mc/8, 256>>>(src, ng + l*Dc, nb + l*Dc, 0, nullptr);

        // GEMM1: Bx + gates (A = A1 only; hallIters = 0; K = 512)
        {
            dim3 g(N1/128, Mc/128);
            mma_gemm<<<g, 256, GEMM_SMEM>>>(a1, a1, w1 + (size_t)l*N1*K1, K1, 0, 0,
                                            bx, gt, gb + (size_t)l*SDc, nullptr, nullptr);
        }

        // fused 3-phase scan (one launch)
        scan_fused<<<64, 1024>>>(l, theta, damp_p, h0, hfin);

        // GEMM2: y = C*hall + D*xn; hall from A2 (16 iters), xn from A1; K = 1536
        {
            dim3 g(N2/128, Mc/128);
            mma_gemm<<<g, 256, GEMM_SMEM>>>(a1, a2, w2 + (size_t)l*N2*K2, K2, 16, 1,
                                            nullptr, nullptr, nullptr, src, hbuf);
        }
    }

    ln_kernel<<<Mc/8, 256>>>(hbuf, og, ob, 1, out);
}

// round 12
// speedup vs baseline: 2.4302x; 1.0219x over previous
#include <cuda_runtime.h>
#include <cuda_fp16.h>
#include <math.h>
#include <cstdint>

#define Lc   8
#define Bc   4
#define Sc   2048
#define Dc   256
#define SDc  512
#define Mc   (Bc*Sc)      // 8192

#define K1   512          // W1 k-dim (xn planes)
#define N1   1536         // 1024 (Bx interleaved) + 512 (gate)
#define K2   1536         // W2 k-dim: C x1024 + D x512
#define N2   512          // interleaved y pairs
#define KA1  512          // A1 storage: xn planes (fp16)
#define KA2  1024         // A2 storage: hall planes (fp16)

// ----------------------------- device scratch --------------------------------
__device__ __half g_A1[(size_t)Mc*KA1];
__device__ __half g_A2[(size_t)Mc*KA2];
__device__ __half g_W1[(size_t)Lc*N1*K1];   // [l][n][k]
__device__ __half g_W2[(size_t)Lc*N2*K2];   // [l][n][k]
__device__ __half g_Bx[(size_t)Mc*1024];    // interleaved (bxr,bxi) fp16
__device__ __half g_gt[(size_t)Mc*512];     // gates fp16
__device__ float g_h [(size_t)Mc*512];      // interleaved activation

// ----------------------------- helpers ----------------------------------------
__device__ __forceinline__ uint32_t s2u(const void* p){
    uint32_t a;
    asm("{ .reg .u64 t; cvta.to.shared.u64 t, %1; cvt.u32.u64 %0, t; }" : "=r"(a) : "l"(p));
    return a;
}
__device__ __forceinline__ void cpa16(uint32_t s, const void* g){
    asm volatile("cp.async.cg.shared.global [%0], [%1], 16;" :: "r"(s), "l"(g));
}
__device__ __forceinline__ uint32_t swz(uint32_t o){ return o ^ ((o >> 3) & 0x70); }

__device__ __forceinline__ void ldsm4(uint32_t* r, uint32_t addr){
    asm volatile("ldmatrix.sync.aligned.m8n8.x4.shared.b16 {%0,%1,%2,%3}, [%4];"
        : "=r"(r[0]), "=r"(r[1]), "=r"(r[2]), "=r"(r[3]) : "r"(addr));
}
__device__ __forceinline__ void mma16816(float* d, const uint32_t* a, const uint32_t* b){
    asm volatile("mma.sync.aligned.m16n8k16.row.col.f32.f16.f16.f32 "
        "{%0,%1,%2,%3}, {%4,%5,%6,%7}, {%8,%9}, {%0,%1,%2,%3};"
        : "+f"(d[0]), "+f"(d[1]), "+f"(d[2]), "+f"(d[3])
        : "r"(a[0]), "r"(a[1]), "r"(a[2]), "r"(a[3]), "r"(b[0]), "r"(b[1]));
}

// ----------------------------- weight prep ------------------------------------
__global__ void prep_w1(const float* __restrict__ BWr, const float* __restrict__ BWi,
                        const float* __restrict__ gW)
{
    size_t i = (size_t)blockIdx.x * blockDim.x + threadIdx.x;
    if (i >= (size_t)Lc*N1*K1) return;
    int kk = (int)(i % K1); size_t r = i / K1; int n = (int)(r % N1); int l = (int)(r / N1);
    float v;
    if (n < 1024) {
        int j = n >> 1, p = n & 1;
        if (kk < 256) v = p ? BWi[((size_t)l*256+kk)*512+j] : BWr[((size_t)l*256+kk)*512+j];
        else { int kr = kk-256; v = p ? BWr[((size_t)l*256+kr)*512+j] : -BWi[((size_t)l*256+kr)*512+j]; }
    } else {
        v = gW[((size_t)l*512+kk)*512 + (n-1024)];
    }
    g_W1[i] = __float2half(v);
}

__global__ void prep_w2(const float* __restrict__ CWr, const float* __restrict__ CWi,
                        const float* __restrict__ DWr, const float* __restrict__ DWi)
{
    size_t i = (size_t)blockIdx.x * blockDim.x + threadIdx.x;
    if (i >= (size_t)Lc*N2*K2) return;
    int k = (int)(i % K2); size_t r = i / K2; int n = (int)(r % N2); int l = (int)(r / N2);
    int j = n >> 1, p = n & 1;
    float v;
    if (k < 1024) {
        int kk = k;
        if (kk < 512) v = p ? CWi[((size_t)l*512+kk)*256+j] : CWr[((size_t)l*512+kk)*256+j];
        else { int ki = kk-512; v = p ? CWr[((size_t)l*512+ki)*256+j] : -CWi[((size_t)l*512+ki)*256+j]; }
    } else {
        int kk = k - 1024;
        if (kk < 256) v = p ? DWi[((size_t)l*256+kk)*256+j] : DWr[((size_t)l*256+kk)*256+j];
        else { int kr = kk-256; v = p ? DWr[((size_t)l*256+kr)*256+j] : -DWi[((size_t)l*256+kr)*256+j]; }
    }
    g_W2[i] = __float2half(v);
}

// ----------------------------- LayerNorm (warp per row) ------------------------
__global__ void ln_kernel(const float* __restrict__ src,
                          const float* __restrict__ gw, const float* __restrict__ bw,
                          int final_mode, float* __restrict__ outInter)
{
    int warp = threadIdx.x >> 5, L = threadIdx.x & 31;
    int m = blockIdx.x * 8 + warp;
    const float4* row = (const float4*)(src + (size_t)m * 512);
    float4 v[4];
    float sr=0.f, si=0.f, qr=0.f, qi=0.f;
    #pragma unroll
    for (int j=0;j<4;j++){
        v[j] = row[L + 32*j];
        sr += v[j].x + v[j].z;  si += v[j].y + v[j].w;
        qr += v[j].x*v[j].x + v[j].z*v[j].z;
        qi += v[j].y*v[j].y + v[j].w*v[j].w;
    }
    #pragma unroll
    for (int o=16;o>0;o>>=1){
        sr += __shfl_xor_sync(0xffffffffu, sr, o);
        si += __shfl_xor_sync(0xffffffffu, si, o);
        qr += __shfl_xor_sync(0xffffffffu, qr, o);
        qi += __shfl_xor_sync(0xffffffffu, qi, o);
    }
    const float inv = 1.f/256.f;
    float mur = sr*inv, mui = si*inv;
    float isr = rsqrtf(qr*inv - mur*mur + 1e-5f);
    float isi = rsqrtf(qi*inv - mui*mui + 1e-5f);

    __half* a1 = g_A1 + (size_t)m * KA1;
    float* ointer = final_mode ? (outInter + (size_t)m*512) : nullptr;

    #pragma unroll
    for (int j=0;j<4;j++){
        int f = L + 32*j;
        float2 g2 = ((const float2*)gw)[f];
        float2 b2 = ((const float2*)bw)[f];
        float nr0 = (v[j].x - mur)*isr*g2.x + b2.x;
        float ni0 = (v[j].y - mui)*isi*g2.x + b2.x;
        float nr1 = (v[j].z - mur)*isr*g2.y + b2.y;
        float ni1 = (v[j].w - mui)*isi*g2.y + b2.y;
        if (final_mode) {
            float4 o4; o4.x=nr0; o4.y=ni0; o4.z=nr1; o4.w=ni1;
            ((float4*)ointer)[f] = o4;
        } else {
            int d0 = 2*f;
            *(__half2*)(a1 + d0)       = __floats2half2_rn(nr0, nr1);  // real plane
            *(__half2*)(a1 + 256 + d0) = __floats2half2_rn(ni0, ni1);  // imag plane
        }
    }
}

// ----------------------------- fused scan ---------------------------------------
// Block = 1024 threads = 32 warps. Block handles (b, 32-sd tile), warp w = chunk w,
// lane = sd within tile (coalesced). fp16 Bx/gt inputs, fp32 recurrence.
__global__ void __launch_bounds__(1024, 1)
scan_fused(int layer, const float* __restrict__ theta, const float* __restrict__ damp,
           const float* __restrict__ h0, float* __restrict__ hfin)
{
    __shared__ float4 scarry[32][33];
    __shared__ float2 sstart[32][33];
    int tid = threadIdx.x;
    int w = tid >> 5, lane = tid & 31;        // w = chunk, lane = sd_local
    int b = blockIdx.x >> 4, sdt = blockIdx.x & 15;
    int sd = sdt*32 + lane;

    float th = theta[layer*SDc+sd], dp = damp[layer*SDc+sd];
    float dm = 0.5f + 0.5f/(1.f+expf(-dp));
    float cd = cosf(th)*dm, sn = sinf(th)*dm;

    int base_row = b*Sc + w*64;

    // Phase 1: chunk carry
    float Ar=1.f, Ai=0.f, Br=0.f, Bi=0.f;
    #pragma unroll 4
    for (int s=0;s<64;s++){
        int row = base_row + s;
        float g = __half2float(g_gt[(size_t)row*512+sd]);
        float2 bx = __half22float2(*(const __half2*)&g_Bx[(size_t)row*1024 + 2*sd]);
        float og = 1.f - g;
        float ar = og*cd, ai = og*sn;
        float nAr = ar*Ar - ai*Ai, nAi = ar*Ai + ai*Ar;
        float nBr = ar*Br - ai*Bi + g*bx.x;
        float nBi = ar*Bi + ai*Br + g*bx.y;
        Ar=nAr; Ai=nAi; Br=nBr; Bi=nBi;
    }
    float4 cv; cv.x=Ar; cv.y=Ai; cv.z=Br; cv.w=Bi;
    scarry[w][lane] = cv;
    __syncthreads();

    // Phase 2: prefix over chunks (warp 0; lane owns its sd)
    if (w == 0) {
        size_t hidx = ((size_t)(layer*Bc+b)*SDc + sd)*2;
        float hr = h0[hidx], hi = h0[hidx+1];
        #pragma unroll
        for (int c=0;c<32;c++){
            float2 s2; s2.x=hr; s2.y=hi;
            sstart[c][lane] = s2;
            float4 cc = scarry[c][lane];
            float nr = cc.x*hr - cc.y*hi + cc.z;
            float ni = cc.x*hi + cc.y*hr + cc.w;
            hr=nr; hi=ni;
        }
        hfin[hidx]   = hr;
        hfin[hidx+1] = hi;
    }
    __syncthreads();

    // Phase 3: rescan with start state, emit fp16 planes
    float2 st0 = sstart[w][lane];
    float hr = st0.x, hi = st0.y;
    #pragma unroll 4
    for (int s=0;s<64;s++){
        int row = base_row + s;
        float g = __half2float(g_gt[(size_t)row*512+sd]);
        float2 bx = __half22float2(*(const __half2*)&g_Bx[(size_t)row*1024 + 2*sd]);
        float tr = hr*cd - hi*sn, ti = hr*sn + hi*cd;
        float og = 1.f - g;
        hr = fmaf(g, bx.x, og*tr);
        hi = fmaf(g, bx.y, og*ti);
        __half* a2 = g_A2 + (size_t)row*KA2;
        a2[sd]     = __float2half(hr);
        a2[512+sd] = __float2half(hi);
    }
}

// ----------------------------- HMMA GEMM ---------------------------------------
// D[m][n] = sum_k A[m][k] * W[n][k]; fp16 1-term.
// A region: ki < hallIters -> A2 (stride 1024), else A1 (stride 512), identity k.
// 128x128 tile, 256 thr (2x4 warps, 64x32), ST=3, 2 CTA/SM.
// mode 0: n<1024 -> oBx (fp16 pairs); n>=1024 -> oGt (fp16) = sigmoid(v + gb)
// mode 1: pairs (2j,2j+1)=(yr,yi): hOut = resid + 0.1*(yr*y + y)
#define ST 3
#define STAGE_BYTES 32768          // A 16KB + B 16KB
#define GEMM_SMEM (ST*STAGE_BYTES) // 96KB -> 2 CTAs/SM

__global__ void __launch_bounds__(256, 2)
mma_gemm(const __half* __restrict__ A1p, const __half* __restrict__ A2p,
         const __half* __restrict__ W, int KW, int hallIters, int mode,
         __half* __restrict__ oBx, __half* __restrict__ oGt, const float* __restrict__ gb,
         const float* __restrict__ resid, float* __restrict__ hOut)
{
    extern __shared__ char smem[];
    uint32_t sb = s2u(smem);
    int tid = threadIdx.x, wid = tid >> 5, L = tid & 31;
    int m0 = blockIdx.y * 128, n0 = blockIdx.x * 128;
    const int NK = KW >> 6;

    // ---- A chunks (4 x 16B per thread per stage) ----
    uint32_t rA[4], cA[4], soffA[4];
    #pragma unroll
    for (int i = 0; i < 4; i++) {
        int q = tid + i*256;              // 0..1023
        int r = q >> 3, c = q & 7;
        rA[i] = (uint32_t)(m0 + r);
        cA[i] = (uint32_t)(c * 8);
        soffA[i] = swz((uint32_t)(r*128 + c*16));
    }
    // ---- B chunks ----
    const __half* gBp[4]; uint32_t soffB[4];
    #pragma unroll
    for (int i = 0; i < 4; i++) {
        int q = (tid + (i+4)*256) & 1023;
        int r = q >> 3, c = q & 7;
        gBp[i] = W + (size_t)(n0 + r)*KW + c*8;
        soffB[i] = 16384u + swz((uint32_t)(r*128 + c*16));
    }

    // ---- ldmatrix lane addressing (SW128) ----
    int wm = wid >> 2, wn = wid & 3;
    int rowA0 = wm*64 + (L & 7) + ((L >> 3) & 1) * 8;
    uint32_t aBase = (uint32_t)rowA0 * 128; uint32_t aS = (uint32_t)(rowA0 & 7);
    uint32_t aC = (uint32_t)(L >> 4);
    int rowB0 = wn*32 + (L & 7) + ((L >> 4) & 1) * 8;
    uint32_t bBase = 16384u + (uint32_t)rowB0 * 128; uint32_t bS = (uint32_t)(rowB0 & 7);
    uint32_t bC = (uint32_t)((L >> 3) & 1);

    float c[4][4][4];
    #pragma unroll
    for (int i=0;i<4;i++)
        #pragma unroll
        for (int j=0;j<4;j++)
            #pragma unroll
            for (int e=0;e<4;e++) c[i][j][e] = 0.f;

    // stage loader: identity k-map within region
    auto load_stage = [&](int ki, uint32_t st){
        const __half* ab; int sh; uint32_t koff;
        if (ki < hallIters) { ab = A2p; sh = 10; koff = (uint32_t)(ki << 6); }
        else { ab = A1p; sh = 9; koff = (uint32_t)((ki - hallIters) << 6); }
        #pragma unroll
        for (int i = 0; i < 4; i++)
            cpa16(st + soffA[i], ab + ((rA[i] << sh) + koff + cA[i]));
        uint32_t kb = (uint32_t)(ki * 64);
        #pragma unroll
        for (int i = 0; i < 4; i++)
            cpa16(st + soffB[i], gBp[i] + kb);
    };

    // ---- prologue: load stages 0,1 ----
    #pragma unroll
    for (int s = 0; s < ST-1; s++) {
        if (s < NK) load_stage(s, sb + s*STAGE_BYTES);
        asm volatile("cp.async.commit_group;" ::: "memory");
    }

    for (int ki = 0; ki < NK; ki++) {
        asm volatile("cp.async.wait_group %0;" :: "n"(ST-2) : "memory");
        __syncthreads();

        uint32_t st = sb + (uint32_t)(ki % ST) * STAGE_BYTES;
        #pragma unroll
        for (int kk = 0; kk < 4; kk++) {
            uint32_t a[4][4], b[2][4];
            uint32_t ca = (uint32_t)(kk*2);
            #pragma unroll
            for (int mt = 0; mt < 4; mt++)
                ldsm4(a[mt], st + aBase + (uint32_t)mt*2048 + (((ca + aC) ^ aS) << 4));
            #pragma unroll
            for (int bt = 0; bt < 2; bt++)
                ldsm4(b[bt], st + bBase + (uint32_t)bt*2048 + (((ca + bC) ^ bS) << 4));
            #pragma unroll
            for (int mt = 0; mt < 4; mt++)
                #pragma unroll
                for (int nt = 0; nt < 4; nt++)
                    mma16816(c[mt][nt], a[mt], &b[nt>>1][(nt&1)*2]);
        }

        int ls = ki + ST - 1;
        if (ls < NK) load_stage(ls, sb + (uint32_t)(ls % ST) * STAGE_BYTES);
        asm volatile("cp.async.commit_group;" ::: "memory");
    }

    // ---- epilogue ----
    int lrow = L >> 2, lcol = (L & 3) * 2;
    int mRow = m0 + wm*64 + lrow;
    int nCol = n0 + wn*32 + lcol;
    #pragma unroll
    for (int mt = 0; mt < 4; mt++) {
        #pragma unroll
        for (int nt = 0; nt < 4; nt++) {
            int row = mRow + mt*16;
            int col = nCol + nt*8;
            float* cc = c[mt][nt];
            if (mode == 0) {
                if (col < 1024) {
                    *(__half2*)&oBx[(size_t)row*1024 + col]     = __floats2half2_rn(cc[0], cc[1]);
                    *(__half2*)&oBx[(size_t)(row+8)*1024 + col] = __floats2half2_rn(cc[2], cc[3]);
                } else {
                    int gc = col - 1024;
                    float b0 = gb[gc], b1 = gb[gc+1];
                    float g00 = 1.f/(1.f+expf(-(cc[0]+b0)));
                    float g01 = 1.f/(1.f+expf(-(cc[1]+b1)));
                    float g10 = 1.f/(1.f+expf(-(cc[2]+b0)));
                    float g11 = 1.f/(1.f+expf(-(cc[3]+b1)));
                    *(__half2*)&oGt[(size_t)row*512 + gc]     = __floats2half2_rn(g00, g01);
                    *(__half2*)&oGt[(size_t)(row+8)*512 + gc] = __floats2half2_rn(g10, g11);
                }
            } else {
                float2 r0 = *(const float2*)&resid[(size_t)row*512 + col];
                float2 r1 = *(const float2*)&resid[(size_t)(row+8)*512 + col];
                float2 v0, v1;
                v0.x = r0.x + 0.1f*(cc[0]*cc[0] + cc[0]);
                v0.y = r0.y + 0.1f*(cc[0]*cc[1] + cc[1]);
                v1.x = r1.x + 0.1f*(cc[2]*cc[2] + cc[2]);
                v1.y = r1.y + 0.1f*(cc[2]*cc[3] + cc[3]);
                *(float2*)&hOut[(size_t)row*512 + col] = v0;
                *(float2*)&hOut[(size_t)(row+8)*512 + col] = v1;
            }
        }
    }
}

// ----------------------------- host ---------------------------------------------
extern "C" void kernel_launch(void* const* d_in, const int* in_sizes, int n_in,
                              void* d_out, int out_size)
{
    const float* x      = (const float*)d_in[0];
    const float* h0     = (const float*)d_in[1];
    const float* theta  = (const float*)d_in[2];
    const float* damp_p = (const float*)d_in[3];
    const float* BWr    = (const float*)d_in[4];
    const float* BWi    = (const float*)d_in[5];
    const float* CWr    = (const float*)d_in[6];
    const float* CWi    = (const float*)d_in[7];
    const float* DWr    = (const float*)d_in[8];
    const float* DWi    = (const float*)d_in[9];
    const float* gW     = (const float*)d_in[10];
    const float* gb     = (const float*)d_in[11];
    const float* ng     = (const float*)d_in[12];
    const float* nb     = (const float*)d_in[13];
    const float* og     = (const float*)d_in[14];
    const float* ob     = (const float*)d_in[15];
    float* out = (float*)d_out;

    cudaFuncSetAttribute(mma_gemm, cudaFuncAttributeMaxDynamicSharedMemorySize, GEMM_SMEM);

    __half *a1, *a2, *w1, *w2, *bx, *gt;
    float *hbuf;
    cudaGetSymbolAddress((void**)&a1, g_A1);
    cudaGetSymbolAddress((void**)&a2, g_A2);
    cudaGetSymbolAddress((void**)&w1, g_W1);
    cudaGetSymbolAddress((void**)&w2, g_W2);
    cudaGetSymbolAddress((void**)&bx, g_Bx);
    cudaGetSymbolAddress((void**)&gt, g_gt);
    cudaGetSymbolAddress((void**)&hbuf, g_h);

    float* hfin = out + (size_t)Mc*Dc*2;

    {
        size_t n1 = (size_t)Lc*N1*K1;
        prep_w1<<<(unsigned)((n1+255)/256), 256>>>(BWr, BWi, gW);
        size_t n2 = (size_t)Lc*N2*K2;
        prep_w2<<<(unsigned)((n2+255)/256), 256>>>(CWr, CWi, DWr, DWi);
    }

    for (int l = 0; l < Lc; l++) {
        const float* src = (l == 0) ? x : hbuf;

        ln_kernel<<<Mc/8, 256>>>(src, ng + l*Dc, nb + l*Dc, 0, nullptr);

        // GEMM1: Bx + gates (A = A1 only; hallIters = 0; K = 512)
        {
            dim3 g(N1/128, Mc/128);
            mma_gemm<<<g, 256, GEMM_SMEM>>>(a1, a1, w1 + (size_t)l*N1*K1, K1, 0, 0,
                                            bx, gt, gb + (size_t)l*SDc, nullptr, nullptr);
        }

        // fused 3-phase scan (one launch)
        scan_fused<<<64, 1024>>>(l, theta, damp_p, h0, hfin);

        // GEMM2: y = C*hall + D*xn; hall from A2 (16 iters), xn from A1; K = 1536
        {
            dim3 g(N2/128, Mc/128);
            mma_gemm<<<g, 256, GEMM_SMEM>>>(a1, a2, w2 + (size_t)l*N2*K2, K2, 16, 1,
                                            nullptr, nullptr, nullptr, src, hbuf);
        }
    }

    ln_kernel<<<Mc/8, 256>>>(hbuf, og, ob, 1, out);
}

// round 14
// speedup vs baseline: 2.6267x; 1.0809x over previous
#include <cuda_runtime.h>
#include <cuda_fp16.h>
#include <math.h>
#include <cstdint>

#define Lc   8
#define Bc   4
#define Sc   2048
#define Dc   256
#define SDc  512
#define Mc   (Bc*Sc)      // 8192

#define K1   512          // W1 k-dim (xn planes)
#define N1   1536         // 1024 (Bx interleaved) + 512 (gate)
#define K2   1536         // W2 k-dim: C x1024 + D x512
#define N2   512          // interleaved y pairs
#define KA1  512          // A1 storage: xn planes (fp16)
#define KA2  1024         // A2 storage: hall planes (fp16)

// ----------------------------- device scratch --------------------------------
__device__ __half g_A1[(size_t)Mc*KA1];
__device__ __half g_A2[(size_t)Mc*KA2];
__device__ __half g_W1[(size_t)Lc*N1*K1];   // [l][n][k]
__device__ __half g_W2[(size_t)Lc*N2*K2];   // [l][n][k]
__device__ __half g_Bx[(size_t)Mc*1024];    // interleaved (bxr,bxi) fp16
__device__ __half g_gt[(size_t)Mc*512];     // gates fp16
__device__ float g_h [(size_t)Mc*512];      // interleaved activation

// ----------------------------- helpers ----------------------------------------
__device__ __forceinline__ uint32_t s2u(const void* p){
    uint32_t a;
    asm("{ .reg .u64 t; cvta.to.shared.u64 t, %1; cvt.u32.u64 %0, t; }" : "=r"(a) : "l"(p));
    return a;
}
__device__ __forceinline__ void cpa16(uint32_t s, const void* g){
    asm volatile("cp.async.cg.shared.global [%0], [%1], 16;" :: "r"(s), "l"(g));
}
__device__ __forceinline__ uint32_t swz(uint32_t o){ return o ^ ((o >> 3) & 0x70); }

__device__ __forceinline__ void ldsm4(uint32_t* r, uint32_t addr){
    asm volatile("ldmatrix.sync.aligned.m8n8.x4.shared.b16 {%0,%1,%2,%3}, [%4];"
        : "=r"(r[0]), "=r"(r[1]), "=r"(r[2]), "=r"(r[3]) : "r"(addr));
}
__device__ __forceinline__ void mma16816(float* d, const uint32_t* a, const uint32_t* b){
    asm volatile("mma.sync.aligned.m16n8k16.row.col.f32.f16.f16.f32 "
        "{%0,%1,%2,%3}, {%4,%5,%6,%7}, {%8,%9}, {%0,%1,%2,%3};"
        : "+f"(d[0]), "+f"(d[1]), "+f"(d[2]), "+f"(d[3])
        : "r"(a[0]), "r"(a[1]), "r"(a[2]), "r"(a[3]), "r"(b[0]), "r"(b[1]));
}

// ----------------------------- weight prep ------------------------------------
__global__ void prep_w1(const float* __restrict__ BWr, const float* __restrict__ BWi,
                        const float* __restrict__ gW)
{
    size_t i = (size_t)blockIdx.x * blockDim.x + threadIdx.x;
    if (i >= (size_t)Lc*N1*K1) return;
    int kk = (int)(i % K1); size_t r = i / K1; int n = (int)(r % N1); int l = (int)(r / N1);
    float v;
    if (n < 1024) {
        int j = n >> 1, p = n & 1;
        if (kk < 256) v = p ? BWi[((size_t)l*256+kk)*512+j] : BWr[((size_t)l*256+kk)*512+j];
        else { int kr = kk-256; v = p ? BWr[((size_t)l*256+kr)*512+j] : -BWi[((size_t)l*256+kr)*512+j]; }
    } else {
        v = gW[((size_t)l*512+kk)*512 + (n-1024)];
    }
    g_W1[i] = __float2half(v);
}

__global__ void prep_w2(const float* __restrict__ CWr, const float* __restrict__ CWi,
                        const float* __restrict__ DWr, const float* __restrict__ DWi)
{
    size_t i = (size_t)blockIdx.x * blockDim.x + threadIdx.x;
    if (i >= (size_t)Lc*N2*K2) return;
    int k = (int)(i % K2); size_t r = i / K2; int n = (int)(r % N2); int l = (int)(r / N2);
    int j = n >> 1, p = n & 1;
    float v;
    if (k < 1024) {
        int kk = k;
        if (kk < 512) v = p ? CWi[((size_t)l*512+kk)*256+j] : CWr[((size_t)l*512+kk)*256+j];
        else { int ki = kk-512; v = p ? CWr[((size_t)l*512+ki)*256+j] : -CWi[((size_t)l*512+ki)*256+j]; }
    } else {
        int kk = k - 1024;
        if (kk < 256) v = p ? DWi[((size_t)l*256+kk)*256+j] : DWr[((size_t)l*256+kk)*256+j];
        else { int kr = kk-256; v = p ? DWr[((size_t)l*256+kr)*256+j] : -DWi[((size_t)l*256+kr)*256+j]; }
    }
    g_W2[i] = __float2half(v);
}

// ----------------------------- LayerNorm (warp per row) ------------------------
__global__ void ln_kernel(const float* __restrict__ src,
                          const float* __restrict__ gw, const float* __restrict__ bw,
                          int final_mode, float* __restrict__ outInter, int mBase)
{
    int warp = threadIdx.x >> 5, L = threadIdx.x & 31;
    int m = mBase + blockIdx.x * 8 + warp;
    const float4* row = (const float4*)(src + (size_t)m * 512);
    float4 v[4];
    float sr=0.f, si=0.f, qr=0.f, qi=0.f;
    #pragma unroll
    for (int j=0;j<4;j++){
        v[j] = row[L + 32*j];
        sr += v[j].x + v[j].z;  si += v[j].y + v[j].w;
        qr += v[j].x*v[j].x + v[j].z*v[j].z;
        qi += v[j].y*v[j].y + v[j].w*v[j].w;
    }
    #pragma unroll
    for (int o=16;o>0;o>>=1){
        sr += __shfl_xor_sync(0xffffffffu, sr, o);
        si += __shfl_xor_sync(0xffffffffu, si, o);
        qr += __shfl_xor_sync(0xffffffffu, qr, o);
        qi += __shfl_xor_sync(0xffffffffu, qi, o);
    }
    const float inv = 1.f/256.f;
    float mur = sr*inv, mui = si*inv;
    float isr = rsqrtf(qr*inv - mur*mur + 1e-5f);
    float isi = rsqrtf(qi*inv - mui*mui + 1e-5f);

    __half* a1 = g_A1 + (size_t)m * KA1;
    float* ointer = final_mode ? (outInter + (size_t)m*512) : nullptr;

    #pragma unroll
    for (int j=0;j<4;j++){
        int f = L + 32*j;
        float2 g2 = ((const float2*)gw)[f];
        float2 b2 = ((const float2*)bw)[f];
        float nr0 = (v[j].x - mur)*isr*g2.x + b2.x;
        float ni0 = (v[j].y - mui)*isi*g2.x + b2.x;
        float nr1 = (v[j].z - mur)*isr*g2.y + b2.y;
        float ni1 = (v[j].w - mui)*isi*g2.y + b2.y;
        if (final_mode) {
            float4 o4; o4.x=nr0; o4.y=ni0; o4.z=nr1; o4.w=ni1;
            ((float4*)ointer)[f] = o4;
        } else {
            int d0 = 2*f;
            *(__half2*)(a1 + d0)       = __floats2half2_rn(nr0, nr1);  // real plane
            *(__half2*)(a1 + 256 + d0) = __floats2half2_rn(ni0, ni1);  // imag plane
        }
    }
}

// ----------------------------- fused scan (per-batch-quarter) ------------------
__global__ void __launch_bounds__(1024, 1)
scan_fused(int layer, const float* __restrict__ theta, const float* __restrict__ damp,
           const float* __restrict__ h0, float* __restrict__ hfin, int b)
{
    __shared__ float4 scarry[32][33];
    __shared__ float2 sstart[32][33];
    int tid = threadIdx.x;
    int w = tid >> 5, lane = tid & 31;        // w = chunk, lane = sd_local
    int sdt = blockIdx.x;
    int sd = sdt*32 + lane;

    float th = theta[layer*SDc+sd], dp = damp[layer*SDc+sd];
    float dm = 0.5f + 0.5f/(1.f+expf(-dp));
    float cd = cosf(th)*dm, sn = sinf(th)*dm;

    int base_row = b*Sc + w*64;

    // Phase 1: chunk carry
    float Ar=1.f, Ai=0.f, Br=0.f, Bi=0.f;
    #pragma unroll 4
    for (int s=0;s<64;s++){
        int row = base_row + s;
        float g = __half2float(g_gt[(size_t)row*512+sd]);
        float2 bx = __half22float2(*(const __half2*)&g_Bx[(size_t)row*1024 + 2*sd]);
        float og = 1.f - g;
        float ar = og*cd, ai = og*sn;
        float nAr = ar*Ar - ai*Ai, nAi = ar*Ai + ai*Ar;
        float nBr = ar*Br - ai*Bi + g*bx.x;
        float nBi = ar*Bi + ai*Br + g*bx.y;
        Ar=nAr; Ai=nAi; Br=nBr; Bi=nBi;
    }
    float4 cv; cv.x=Ar; cv.y=Ai; cv.z=Br; cv.w=Bi;
    scarry[w][lane] = cv;
    __syncthreads();

    // Phase 2: prefix over chunks (warp 0; lane owns its sd)
    if (w == 0) {
        size_t hidx = ((size_t)(layer*Bc+b)*SDc + sd)*2;
        float hr = h0[hidx], hi = h0[hidx+1];
        #pragma unroll
        for (int c=0;c<32;c++){
            float2 s2; s2.x=hr; s2.y=hi;
            sstart[c][lane] = s2;
            float4 cc = scarry[c][lane];
            float nr = cc.x*hr - cc.y*hi + cc.z;
            float ni = cc.x*hi + cc.y*hr + cc.w;
            hr=nr; hi=ni;
        }
        hfin[hidx]   = hr;
        hfin[hidx+1] = hi;
    }
    __syncthreads();

    // Phase 3: rescan with start state, emit fp16 planes
    float2 st0 = sstart[w][lane];
    float hr = st0.x, hi = st0.y;
    #pragma unroll 4
    for (int s=0;s<64;s++){
        int row = base_row + s;
        float g = __half2float(g_gt[(size_t)row*512+sd]);
        float2 bx = __half22float2(*(const __half2*)&g_Bx[(size_t)row*1024 + 2*sd]);
        float tr = hr*cd - hi*sn, ti = hr*sn + hi*cd;
        float og = 1.f - g;
        hr = fmaf(g, bx.x, og*tr);
        hi = fmaf(g, bx.y, og*ti);
        __half* a2 = g_A2 + (size_t)row*KA2;
        a2[sd]     = __float2half(hr);
        a2[512+sd] = __float2half(hi);
    }
}

// ----------------------------- HMMA GEMM ---------------------------------------
#define ST 3
#define STAGE_BYTES 32768          // A 16KB + B 16KB
#define GEMM_SMEM (ST*STAGE_BYTES) // 96KB -> 2 CTAs/SM

__global__ void __launch_bounds__(256, 2)
mma_gemm(const __half* __restrict__ A1p, const __half* __restrict__ A2p,
         const __half* __restrict__ W, int KW, int hallIters, int mode,
         __half* __restrict__ oBx, __half* __restrict__ oGt, const float* __restrict__ gb,
         const float* __restrict__ resid, float* __restrict__ hOut, int mBase)
{
    extern __shared__ char smem[];
    uint32_t sb = s2u(smem);
    int tid = threadIdx.x, wid = tid >> 5, L = tid & 31;
    int m0 = mBase + blockIdx.y * 128, n0 = blockIdx.x * 128;
    const int NK = KW >> 6;

    // ---- A chunks (4 x 16B per thread per stage) ----
    uint32_t rA[4], cA[4], soffA[4];
    #pragma unroll
    for (int i = 0; i < 4; i++) {
        int q = tid + i*256;              // 0..1023
        int r = q >> 3, c = q & 7;
        rA[i] = (uint32_t)(m0 + r);
        cA[i] = (uint32_t)(c * 8);
        soffA[i] = swz((uint32_t)(r*128 + c*16));
    }
    // ---- B chunks ----
    const __half* gBp[4]; uint32_t soffB[4];
    #pragma unroll
    for (int i = 0; i < 4; i++) {
        int q = (tid + (i+4)*256) & 1023;
        int r = q >> 3, c = q & 7;
        gBp[i] = W + (size_t)(n0 + r)*KW + c*8;
        soffB[i] = 16384u + swz((uint32_t)(r*128 + c*16));
    }

    // ---- ldmatrix lane addressing (SW128) ----
    int wm = wid >> 2, wn = wid & 3;
    int rowA0 = wm*64 + (L & 7) + ((L >> 3) & 1) * 8;
    uint32_t aBase = (uint32_t)rowA0 * 128; uint32_t aS = (uint32_t)(rowA0 & 7);
    uint32_t aC = (uint32_t)(L >> 4);
    int rowB0 = wn*32 + (L & 7) + ((L >> 4) & 1) * 8;
    uint32_t bBase = 16384u + (uint32_t)rowB0 * 128; uint32_t bS = (uint32_t)(rowB0 & 7);
    uint32_t bC = (uint32_t)((L >> 3) & 1);

    float c[4][4][4];
    #pragma unroll
    for (int i=0;i<4;i++)
        #pragma unroll
        for (int j=0;j<4;j++)
            #pragma unroll
            for (int e=0;e<4;e++) c[i][j][e] = 0.f;

    // stage loader: identity k-map within region
    auto load_stage = [&](int ki, uint32_t st){
        const __half* ab; int sh; uint32_t koff;
        if (ki < hallIters) { ab = A2p; sh = 10; koff = (uint32_t)(ki << 6); }
        else { ab = A1p; sh = 9; koff = (uint32_t)((ki - hallIters) << 6); }
        #pragma unroll
        for (int i = 0; i < 4; i++)
            cpa16(st + soffA[i], ab + ((rA[i] << sh) + koff + cA[i]));
        uint32_t kb = (uint32_t)(ki * 64);
        #pragma unroll
        for (int i = 0; i < 4; i++)
            cpa16(st + soffB[i], gBp[i] + kb);
    };

    // ---- prologue: load stages 0,1 ----
    #pragma unroll
    for (int s = 0; s < ST-1; s++) {
        if (s < NK) load_stage(s, sb + s*STAGE_BYTES);
        asm volatile("cp.async.commit_group;" ::: "memory");
    }

    for (int ki = 0; ki < NK; ki++) {
        asm volatile("cp.async.wait_group %0;" :: "n"(ST-2) : "memory");
        __syncthreads();

        uint32_t st = sb + (uint32_t)(ki % ST) * STAGE_BYTES;
        #pragma unroll
        for (int kk = 0; kk < 4; kk++) {
            uint32_t a[4][4], b[2][4];
            uint32_t ca = (uint32_t)(kk*2);
            #pragma unroll
            for (int mt = 0; mt < 4; mt++)
                ldsm4(a[mt], st + aBase + (uint32_t)mt*2048 + (((ca + aC) ^ aS) << 4));
            #pragma unroll
            for (int bt = 0; bt < 2; bt++)
                ldsm4(b[bt], st + bBase + (uint32_t)bt*2048 + (((ca + bC) ^ bS) << 4));
            #pragma unroll
            for (int mt = 0; mt < 4; mt++)
                #pragma unroll
                for (int nt = 0; nt < 4; nt++)
                    mma16816(c[mt][nt], a[mt], &b[nt>>1][(nt&1)*2]);
        }

        int ls = ki + ST - 1;
        if (ls < NK) load_stage(ls, sb + (uint32_t)(ls % ST) * STAGE_BYTES);
        asm volatile("cp.async.commit_group;" ::: "memory");
    }

    // ---- epilogue ----
    int lrow = L >> 2, lcol = (L & 3) * 2;
    int mRow = m0 + wm*64 + lrow;
    int nCol = n0 + wn*32 + lcol;
    #pragma unroll
    for (int mt = 0; mt < 4; mt++) {
        #pragma unroll
        for (int nt = 0; nt < 4; nt++) {
            int row = mRow + mt*16;
            int col = nCol + nt*8;
            float* cc = c[mt][nt];
            if (mode == 0) {
                if (col < 1024) {
                    *(__half2*)&oBx[(size_t)row*1024 + col]     = __floats2half2_rn(cc[0], cc[1]);
                    *(__half2*)&oBx[(size_t)(row+8)*1024 + col] = __floats2half2_rn(cc[2], cc[3]);
                } else {
                    int gc = col - 1024;
                    float b0 = gb[gc], b1 = gb[gc+1];
                    float g00 = 1.f/(1.f+expf(-(cc[0]+b0)));
                    float g01 = 1.f/(1.f+expf(-(cc[1]+b1)));
                    float g10 = 1.f/(1.f+expf(-(cc[2]+b0)));
                    float g11 = 1.f/(1.f+expf(-(cc[3]+b1)));
                    *(__half2*)&oGt[(size_t)row*512 + gc]     = __floats2half2_rn(g00, g01);
                    *(__half2*)&oGt[(size_t)(row+8)*512 + gc] = __floats2half2_rn(g10, g11);
                }
            } else {
                float2 r0 = *(const float2*)&resid[(size_t)row*512 + col];
                float2 r1 = *(const float2*)&resid[(size_t)(row+8)*512 + col];
                float2 v0, v1;
                v0.x = r0.x + 0.1f*(cc[0]*cc[0] + cc[0]);
                v0.y = r0.y + 0.1f*(cc[0]*cc[1] + cc[1]);
                v1.x = r1.x + 0.1f*(cc[2]*cc[2] + cc[2]);
                v1.y = r1.y + 0.1f*(cc[2]*cc[3] + cc[3]);
                *(float2*)&hOut[(size_t)row*512 + col] = v0;
                *(float2*)&hOut[(size_t)(row+8)*512 + col] = v1;
            }
        }
    }
}

// ----------------------------- host ---------------------------------------------
extern "C" void kernel_launch(void* const* d_in, const int* in_sizes, int n_in,
                              void* d_out, int out_size)
{
    const float* x      = (const float*)d_in[0];
    const float* h0     = (const float*)d_in[1];
    const float* theta  = (const float*)d_in[2];
    const float* damp_p = (const float*)d_in[3];
    const float* BWr    = (const float*)d_in[4];
    const float* BWi    = (const float*)d_in[5];
    const float* CWr    = (const float*)d_in[6];
    const float* CWi    = (const float*)d_in[7];
    const float* DWr    = (const float*)d_in[8];
    const float* DWi    = (const float*)d_in[9];
    const float* gW     = (const float*)d_in[10];
    const float* gb     = (const float*)d_in[11];
    const float* ng     = (const float*)d_in[12];
    const float* nb     = (const float*)d_in[13];
    const float* og     = (const float*)d_in[14];
    const float* ob     = (const float*)d_in[15];
    float* out = (float*)d_out;

    cudaFuncSetAttribute(mma_gemm, cudaFuncAttributeMaxDynamicSharedMemorySize, GEMM_SMEM);

    __half *a1, *a2, *w1, *w2, *bx, *gt;
    float *hbuf;
    cudaGetSymbolAddress((void**)&a1, g_A1);
    cudaGetSymbolAddress((void**)&a2, g_A2);
    cudaGetSymbolAddress((void**)&w1, g_W1);
    cudaGetSymbolAddress((void**)&w2, g_W2);
    cudaGetSymbolAddress((void**)&bx, g_Bx);
    cudaGetSymbolAddress((void**)&gt, g_gt);
    cudaGetSymbolAddress((void**)&hbuf, g_h);

    float* hfin = out + (size_t)Mc*Dc*2;

    // Streams/events created ONCE (first call = correctness run, before graph
    // capture). Reused verbatim on the capture call, so no device-memory delta
    // occurs during capture. The captured work is identical on every call.
    static cudaStream_t s1 = nullptr, s2 = nullptr, s3 = nullptr;
    static cudaEvent_t evRoot = nullptr, evJ0 = nullptr, evJ1 = nullptr, evJ2 = nullptr;
    if (s1 == nullptr) {
        cudaStreamCreateWithFlags(&s1, cudaStreamNonBlocking);
        cudaStreamCreateWithFlags(&s2, cudaStreamNonBlocking);
        cudaStreamCreateWithFlags(&s3, cudaStreamNonBlocking);
        cudaEventCreateWithFlags(&evRoot, cudaEventDisableTiming);
        cudaEventCreateWithFlags(&evJ0, cudaEventDisableTiming);
        cudaEventCreateWithFlags(&evJ1, cudaEventDisableTiming);
        cudaEventCreateWithFlags(&evJ2, cudaEventDisableTiming);
    }
    cudaStream_t st[4] = { 0, s1, s2, s3 };
    cudaEvent_t evJ[3] = { evJ0, evJ1, evJ2 };

    {
        size_t n1 = (size_t)Lc*N1*K1;
        prep_w1<<<(unsigned)((n1+255)/256), 256>>>(BWr, BWi, gW);
        size_t n2 = (size_t)Lc*N2*K2;
        prep_w2<<<(unsigned)((n2+255)/256), 256>>>(CWr, CWi, DWr, DWi);
    }

    // fork
    cudaEventRecord(evRoot, st[0]);
    for (int b = 1; b < 4; b++) cudaStreamWaitEvent(st[b], evRoot, 0);

    // 4 independent per-batch pipelines
    for (int b = 0; b < 4; b++) {
        int mBase = b * Sc;
        for (int l = 0; l < Lc; l++) {
            const float* src = (l == 0) ? x : hbuf;

            ln_kernel<<<Sc/8, 256, 0, st[b]>>>(src, ng + l*Dc, nb + l*Dc, 0, nullptr, mBase);

            {   // GEMM1: Bx + gates (A = A1; K = 512)
                dim3 g(N1/128, Sc/128);
                mma_gemm<<<g, 256, GEMM_SMEM, st[b]>>>(a1, a1, w1 + (size_t)l*N1*K1, K1, 0, 0,
                                                       bx, gt, gb + (size_t)l*SDc,
                                                       nullptr, nullptr, mBase);
            }

            scan_fused<<<16, 1024, 0, st[b]>>>(l, theta, damp_p, h0, hfin, b);

            {   // GEMM2: y = C*hall + D*xn; K = 1536, hall 16 iters
                dim3 g(N2/128, Sc/128);
                mma_gemm<<<g, 256, GEMM_SMEM, st[b]>>>(a1, a2, w2 + (size_t)l*N2*K2, K2, 16, 1,
                                                       nullptr, nullptr, nullptr,
                                                       src, hbuf, mBase);
            }
        }
    }

    // join
    for (int b = 1; b < 4; b++) {
        cudaEventRecord(evJ[b-1], st[b]);
        cudaStreamWaitEvent(st[0], evJ[b-1], 0);
    }

    // final LayerNorm over all rows
    ln_kernel<<<Mc/8, 256, 0, st[0]>>>(hbuf, og, ob, 1, out, 0);
}

// round 16
// speedup vs baseline: 2.7441x; 1.0447x over previous
#include <cuda_runtime.h>
#include <cuda_fp16.h>
#include <math.h>
#include <cstdint>

#define Lc   8
#define Bc   4
#define Sc   2048
#define Dc   256
#define SDc  512
#define Mc   (Bc*Sc)      // 8192

#define K1   512          // W1 k-dim (xn planes)
#define N1   1536         // 1024 (Bx interleaved) + 512 (gate)
#define K2   1536         // W2 k-dim: C x1024 + D x512
#define N2   512          // interleaved y pairs
#define KA1  512          // A1 storage: xn planes (fp16)
#define KA2  1024         // A2 storage: hall planes (fp16)

// ----------------------------- device scratch --------------------------------
__device__ __half g_A1[(size_t)Mc*KA1];
__device__ __half g_A2[(size_t)Mc*KA2];
__device__ __half g_W1[(size_t)Lc*N1*K1];   // [l][n][k]
__device__ __half g_W2[(size_t)Lc*N2*K2];   // [l][n][k]
__device__ __half g_Bx[(size_t)Mc*1024];    // interleaved (bxr,bxi) fp16
__device__ __half g_gt[(size_t)Mc*512];     // gates fp16
__device__ float g_h [(size_t)Mc*512];      // interleaved activation

// ----------------------------- helpers ----------------------------------------
__device__ __forceinline__ uint32_t s2u(const void* p){
    uint32_t a;
    asm("{ .reg .u64 t; cvta.to.shared.u64 t, %1; cvt.u32.u64 %0, t; }" : "=r"(a) : "l"(p));
    return a;
}
__device__ __forceinline__ void cpa16(uint32_t s, const void* g){
    asm volatile("cp.async.cg.shared.global [%0], [%1], 16;" :: "r"(s), "l"(g));
}
__device__ __forceinline__ uint32_t swz(uint32_t o){ return o ^ ((o >> 3) & 0x70); }

__device__ __forceinline__ void ldsm4(uint32_t* r, uint32_t addr){
    asm volatile("ldmatrix.sync.aligned.m8n8.x4.shared.b16 {%0,%1,%2,%3}, [%4];"
        : "=r"(r[0]), "=r"(r[1]), "=r"(r[2]), "=r"(r[3]) : "r"(addr));
}
__device__ __forceinline__ void mma16816(float* d, const uint32_t* a, const uint32_t* b){
    asm volatile("mma.sync.aligned.m16n8k16.row.col.f32.f16.f16.f32 "
        "{%0,%1,%2,%3}, {%4,%5,%6,%7}, {%8,%9}, {%0,%1,%2,%3};"
        : "+f"(d[0]), "+f"(d[1]), "+f"(d[2]), "+f"(d[3])
        : "r"(a[0]), "r"(a[1]), "r"(a[2]), "r"(a[3]), "r"(b[0]), "r"(b[1]));
}

// ----------------------------- weight prep (coalesced transposes) --------------
// Complex expand-transpose: src (R,I) are [Ks, J] row-major fp32. Output rows
// n = 2j+p (p=0 real, p=1 imag), cols k = kbase + half*Ks + kr:
//   p0h0: R[kr][j]   p0h1: -I[kr][j]   p1h0: I[kr][j]   p1h1: R[kr][j]
__global__ void prep_cplx(const float* __restrict__ srcR, const float* __restrict__ srcI,
                          __half* __restrict__ dst, int Ks, int J, int Kout, int kbase,
                          size_t srcLS, size_t dstLS)
{
    __shared__ float sR[32][33], sI[32][33];
    int l = blockIdx.z;
    int j0 = blockIdx.x * 32, kr0 = blockIdx.y * 32;
    int tx = threadIdx.x, ty = threadIdx.y;
    const float* R = srcR + (size_t)l * srcLS;
    const float* I = srcI + (size_t)l * srcLS;
    #pragma unroll
    for (int i = 0; i < 4; i++) {
        int kr = kr0 + ty + 8*i;
        sR[ty+8*i][tx] = R[(size_t)kr * J + j0 + tx];
        sI[ty+8*i][tx] = I[(size_t)kr * J + j0 + tx];
    }
    __syncthreads();
    __half* D = dst + (size_t)l * dstLS;
    #pragma unroll
    for (int i = 0; i < 4; i++) {
        int jj = ty + 8*i;
        float r  = sR[tx][jj];
        float vi = sI[tx][jj];
        size_t b0 = (size_t)(2*(j0+jj)) * Kout + kbase + kr0 + tx;   // p=0
        size_t b1 = b0 + Kout;                                        // p=1
        D[b0]      = __float2half(r);
        D[b0 + Ks] = __float2half(-vi);
        D[b1]      = __float2half(vi);
        D[b1 + Ks] = __float2half(r);
    }
}

// Real transpose: out[nbase + c][r] = src[r][c]
__global__ void prep_real(const float* __restrict__ src, __half* __restrict__ dst,
                          int Cn, int Kout, int nbase, size_t srcLS, size_t dstLS)
{
    __shared__ float s[32][33];
    int l = blockIdx.z;
    int c0 = blockIdx.x * 32, r0 = blockIdx.y * 32;
    int tx = threadIdx.x, ty = threadIdx.y;
    const float* S = src + (size_t)l * srcLS;
    #pragma unroll
    for (int i = 0; i < 4; i++)
        s[ty+8*i][tx] = S[(size_t)(r0+ty+8*i) * Cn + c0 + tx];
    __syncthreads();
    __half* D = dst + (size_t)l * dstLS;
    #pragma unroll
    for (int i = 0; i < 4; i++) {
        int cc = ty + 8*i;
        D[(size_t)(nbase + c0 + cc) * Kout + r0 + tx] = __float2half(s[tx][cc]);
    }
}

// ----------------------------- LayerNorm (warp per row) ------------------------
__global__ void ln_kernel(const float* __restrict__ src,
                          const float* __restrict__ gw, const float* __restrict__ bw,
                          int final_mode, float* __restrict__ outInter, int mBase)
{
    int warp = threadIdx.x >> 5, L = threadIdx.x & 31;
    int m = mBase + blockIdx.x * 8 + warp;
    const float4* row = (const float4*)(src + (size_t)m * 512);
    float4 v[4];
    float sr=0.f, si=0.f, qr=0.f, qi=0.f;
    #pragma unroll
    for (int j=0;j<4;j++){
        v[j] = row[L + 32*j];
        sr += v[j].x + v[j].z;  si += v[j].y + v[j].w;
        qr += v[j].x*v[j].x + v[j].z*v[j].z;
        qi += v[j].y*v[j].y + v[j].w*v[j].w;
    }
    #pragma unroll
    for (int o=16;o>0;o>>=1){
        sr += __shfl_xor_sync(0xffffffffu, sr, o);
        si += __shfl_xor_sync(0xffffffffu, si, o);
        qr += __shfl_xor_sync(0xffffffffu, qr, o);
        qi += __shfl_xor_sync(0xffffffffu, qi, o);
    }
    const float inv = 1.f/256.f;
    float mur = sr*inv, mui = si*inv;
    float isr = rsqrtf(qr*inv - mur*mur + 1e-5f);
    float isi = rsqrtf(qi*inv - mui*mui + 1e-5f);

    __half* a1 = g_A1 + (size_t)m * KA1;
    float* ointer = final_mode ? (outInter + (size_t)m*512) : nullptr;

    #pragma unroll
    for (int j=0;j<4;j++){
        int f = L + 32*j;
        float2 g2 = ((const float2*)gw)[f];
        float2 b2 = ((const float2*)bw)[f];
        float nr0 = (v[j].x - mur)*isr*g2.x + b2.x;
        float ni0 = (v[j].y - mui)*isi*g2.x + b2.x;
        float nr1 = (v[j].z - mur)*isr*g2.y + b2.y;
        float ni1 = (v[j].w - mui)*isi*g2.y + b2.y;
        if (final_mode) {
            float4 o4; o4.x=nr0; o4.y=ni0; o4.z=nr1; o4.w=ni1;
            ((float4*)ointer)[f] = o4;
        } else {
            int d0 = 2*f;
            *(__half2*)(a1 + d0)       = __floats2half2_rn(nr0, nr1);  // real plane
            *(__half2*)(a1 + 256 + d0) = __floats2half2_rn(ni0, ni1);  // imag plane
        }
    }
}

// ----------------------------- fused scan (per-batch-quarter) ------------------
__global__ void __launch_bounds__(1024, 1)
scan_fused(int layer, const float* __restrict__ theta, const float* __restrict__ damp,
           const float* __restrict__ h0, float* __restrict__ hfin, int b)
{
    __shared__ float4 scarry[32][33];
    __shared__ float2 sstart[32][33];
    int tid = threadIdx.x;
    int w = tid >> 5, lane = tid & 31;        // w = chunk, lane = sd_local
    int sdt = blockIdx.x;
    int sd = sdt*32 + lane;

    float th = theta[layer*SDc+sd], dp = damp[layer*SDc+sd];
    float dm = 0.5f + 0.5f/(1.f+expf(-dp));
    float cd = cosf(th)*dm, sn = sinf(th)*dm;

    int base_row = b*Sc + w*64;

    // Phase 1: chunk carry
    float Ar=1.f, Ai=0.f, Br=0.f, Bi=0.f;
    #pragma unroll 4
    for (int s=0;s<64;s++){
        int row = base_row + s;
        float g = __half2float(g_gt[(size_t)row*512+sd]);
        float2 bx = __half22float2(*(const __half2*)&g_Bx[(size_t)row*1024 + 2*sd]);
        float og = 1.f - g;
        float ar = og*cd, ai = og*sn;
        float nAr = ar*Ar - ai*Ai, nAi = ar*Ai + ai*Ar;
        float nBr = ar*Br - ai*Bi + g*bx.x;
        float nBi = ar*Bi + ai*Br + g*bx.y;
        Ar=nAr; Ai=nAi; Br=nBr; Bi=nBi;
    }
    float4 cv; cv.x=Ar; cv.y=Ai; cv.z=Br; cv.w=Bi;
    scarry[w][lane] = cv;
    __syncthreads();

    // Phase 2: prefix over chunks (warp 0; lane owns its sd)
    if (w == 0) {
        size_t hidx = ((size_t)(layer*Bc+b)*SDc + sd)*2;
        float hr = h0[hidx], hi = h0[hidx+1];
        #pragma unroll
        for (int c=0;c<32;c++){
            float2 s2; s2.x=hr; s2.y=hi;
            sstart[c][lane] = s2;
            float4 cc = scarry[c][lane];
            float nr = cc.x*hr - cc.y*hi + cc.z;
            float ni = cc.x*hi + cc.y*hr + cc.w;
            hr=nr; hi=ni;
        }
        hfin[hidx]   = hr;
        hfin[hidx+1] = hi;
    }
    __syncthreads();

    // Phase 3: rescan with start state, emit fp16 planes
    float2 st0 = sstart[w][lane];
    float hr = st0.x, hi = st0.y;
    #pragma unroll 4
    for (int s=0;s<64;s++){
        int row = base_row + s;
        float g = __half2float(g_gt[(size_t)row*512+sd]);
        float2 bx = __half22float2(*(const __half2*)&g_Bx[(size_t)row*1024 + 2*sd]);
        float tr = hr*cd - hi*sn, ti = hr*sn + hi*cd;
        float og = 1.f - g;
        hr = fmaf(g, bx.x, og*tr);
        hi = fmaf(g, bx.y, og*ti);
        __half* a2 = g_A2 + (size_t)row*KA2;
        a2[sd]     = __float2half(hr);
        a2[512+sd] = __float2half(hi);
    }
}

// ----------------------------- HMMA GEMM ---------------------------------------
#define ST 3
#define STAGE_BYTES 32768          // A 16KB + B 16KB
#define GEMM_SMEM (ST*STAGE_BYTES) // 96KB -> 2 CTAs/SM

__global__ void __launch_bounds__(256, 2)
mma_gemm(const __half* __restrict__ A1p, const __half* __restrict__ A2p,
         const __half* __restrict__ W, int KW, int hallIters, int mode,
         __half* __restrict__ oBx, __half* __restrict__ oGt, const float* __restrict__ gb,
         const float* __restrict__ resid, float* __restrict__ hOut, int mBase)
{
    extern __shared__ char smem[];
    uint32_t sb = s2u(smem);
    int tid = threadIdx.x, wid = tid >> 5, L = tid & 31;
    int m0 = mBase + blockIdx.y * 128, n0 = blockIdx.x * 128;
    const int NK = KW >> 6;

    // ---- A chunks (4 x 16B per thread per stage) ----
    uint32_t rA[4], cA[4], soffA[4];
    #pragma unroll
    for (int i = 0; i < 4; i++) {
        int q = tid + i*256;              // 0..1023
        int r = q >> 3, c = q & 7;
        rA[i] = (uint32_t)(m0 + r);
        cA[i] = (uint32_t)(c * 8);
        soffA[i] = swz((uint32_t)(r*128 + c*16));
    }
    // ---- B chunks ----
    const __half* gBp[4]; uint32_t soffB[4];
    #pragma unroll
    for (int i = 0; i < 4; i++) {
        int q = (tid + (i+4)*256) & 1023;
        int r = q >> 3, c = q & 7;
        gBp[i] = W + (size_t)(n0 + r)*KW + c*8;
        soffB[i] = 16384u + swz((uint32_t)(r*128 + c*16));
    }

    // ---- ldmatrix lane addressing (SW128) ----
    int wm = wid >> 2, wn = wid & 3;
    int rowA0 = wm*64 + (L & 7) + ((L >> 3) & 1) * 8;
    uint32_t aBase = (uint32_t)rowA0 * 128; uint32_t aS = (uint32_t)(rowA0 & 7);
    uint32_t aC = (uint32_t)(L >> 4);
    int rowB0 = wn*32 + (L & 7) + ((L >> 4) & 1) * 8;
    uint32_t bBase = 16384u + (uint32_t)rowB0 * 128; uint32_t bS = (uint32_t)(rowB0 & 7);
    uint32_t bC = (uint32_t)((L >> 3) & 1);

    float c[4][4][4];
    #pragma unroll
    for (int i=0;i<4;i++)
        #pragma unroll
        for (int j=0;j<4;j++)
            #pragma unroll
            for (int e=0;e<4;e++) c[i][j][e] = 0.f;

    // stage loader: identity k-map within region
    auto load_stage = [&](int ki, uint32_t st){
        const __half* ab; int sh; uint32_t koff;
        if (ki < hallIters) { ab = A2p; sh = 10; koff = (uint32_t)(ki << 6); }
        else { ab = A1p; sh = 9; koff = (uint32_t)((ki - hallIters) << 6); }
        #pragma unroll
        for (int i = 0; i < 4; i++)
            cpa16(st + soffA[i], ab + ((rA[i] << sh) + koff + cA[i]));
        uint32_t kb = (uint32_t)(ki * 64);
        #pragma unroll
        for (int i = 0; i < 4; i++)
            cpa16(st + soffB[i], gBp[i] + kb);
    };

    // ---- prologue: load stages 0,1 ----
    #pragma unroll
    for (int s = 0; s < ST-1; s++) {
        if (s < NK) load_stage(s, sb + s*STAGE_BYTES);
        asm volatile("cp.async.commit_group;" ::: "memory");
    }

    for (int ki = 0; ki < NK; ki++) {
        asm volatile("cp.async.wait_group %0;" :: "n"(ST-2) : "memory");
        __syncthreads();

        uint32_t st = sb + (uint32_t)(ki % ST) * STAGE_BYTES;
        #pragma unroll
        for (int kk = 0; kk < 4; kk++) {
            uint32_t a[4][4], b[2][4];
            uint32_t ca = (uint32_t)(kk*2);
            #pragma unroll
            for (int mt = 0; mt < 4; mt++)
                ldsm4(a[mt], st + aBase + (uint32_t)mt*2048 + (((ca + aC) ^ aS) << 4));
            #pragma unroll
            for (int bt = 0; bt < 2; bt++)
                ldsm4(b[bt], st + bBase + (uint32_t)bt*2048 + (((ca + bC) ^ bS) << 4));
            #pragma unroll
            for (int mt = 0; mt < 4; mt++)
                #pragma unroll
                for (int nt = 0; nt < 4; nt++)
                    mma16816(c[mt][nt], a[mt], &b[nt>>1][(nt&1)*2]);
        }

        int ls = ki + ST - 1;
        if (ls < NK) load_stage(ls, sb + (uint32_t)(ls % ST) * STAGE_BYTES);
        asm volatile("cp.async.commit_group;" ::: "memory");
    }

    // ---- epilogue ----
    int lrow = L >> 2, lcol = (L & 3) * 2;
    int mRow = m0 + wm*64 + lrow;
    int nCol = n0 + wn*32 + lcol;
    #pragma unroll
    for (int mt = 0; mt < 4; mt++) {
        #pragma unroll
        for (int nt = 0; nt < 4; nt++) {
            int row = mRow + mt*16;
            int col = nCol + nt*8;
            float* cc = c[mt][nt];
            if (mode == 0) {
                if (col < 1024) {
                    *(__half2*)&oBx[(size_t)row*1024 + col]     = __floats2half2_rn(cc[0], cc[1]);
                    *(__half2*)&oBx[(size_t)(row+8)*1024 + col] = __floats2half2_rn(cc[2], cc[3]);
                } else {
                    int gc = col - 1024;
                    float b0 = gb[gc], b1 = gb[gc+1];
                    float g00 = 1.f/(1.f+expf(-(cc[0]+b0)));
                    float g01 = 1.f/(1.f+expf(-(cc[1]+b1)));
                    float g10 = 1.f/(1.f+expf(-(cc[2]+b0)));
                    float g11 = 1.f/(1.f+expf(-(cc[3]+b1)));
                    *(__half2*)&oGt[(size_t)row*512 + gc]     = __floats2half2_rn(g00, g01);
                    *(__half2*)&oGt[(size_t)(row+8)*512 + gc] = __floats2half2_rn(g10, g11);
                }
            } else {
                float2 r0 = *(const float2*)&resid[(size_t)row*512 + col];
                float2 r1 = *(const float2*)&resid[(size_t)(row+8)*512 + col];
                float2 v0, v1;
                v0.x = r0.x + 0.1f*(cc[0]*cc[0] + cc[0]);
                v0.y = r0.y + 0.1f*(cc[0]*cc[1] + cc[1]);
                v1.x = r1.x + 0.1f*(cc[2]*cc[2] + cc[2]);
                v1.y = r1.y + 0.1f*(cc[2]*cc[3] + cc[3]);
                *(float2*)&hOut[(size_t)row*512 + col] = v0;
                *(float2*)&hOut[(size_t)(row+8)*512 + col] = v1;
            }
        }
    }
}

// ----------------------------- host ---------------------------------------------
extern "C" void kernel_launch(void* const* d_in, const int* in_sizes, int n_in,
                              void* d_out, int out_size)
{
    const float* x      = (const float*)d_in[0];
    const float* h0     = (const float*)d_in[1];
    const float* theta  = (const float*)d_in[2];
    const float* damp_p = (const float*)d_in[3];
    const float* BWr    = (const float*)d_in[4];
    const float* BWi    = (const float*)d_in[5];
    const float* CWr    = (const float*)d_in[6];
    const float* CWi    = (const float*)d_in[7];
    const float* DWr    = (const float*)d_in[8];
    const float* DWi    = (const float*)d_in[9];
    const float* gW     = (const float*)d_in[10];
    const float* gb     = (const float*)d_in[11];
    const float* ng     = (const float*)d_in[12];
    const float* nb     = (const float*)d_in[13];
    const float* og     = (const float*)d_in[14];
    const float* ob     = (const float*)d_in[15];
    float* out = (float*)d_out;

    cudaFuncSetAttribute(mma_gemm, cudaFuncAttributeMaxDynamicSharedMemorySize, GEMM_SMEM);

    __half *a1, *a2, *w1, *w2, *bx, *gt;
    float *hbuf;
    cudaGetSymbolAddress((void**)&a1, g_A1);
    cudaGetSymbolAddress((void**)&a2, g_A2);
    cudaGetSymbolAddress((void**)&w1, g_W1);
    cudaGetSymbolAddress((void**)&w2, g_W2);
    cudaGetSymbolAddress((void**)&bx, g_Bx);
    cudaGetSymbolAddress((void**)&gt, g_gt);
    cudaGetSymbolAddress((void**)&hbuf, g_h);

    float* hfin = out + (size_t)Mc*Dc*2;

    // EXACT R14 stream/event topology (proven clean with harness + graph):
    // created ONCE on the correctness run, reused on the capture call.
    static cudaStream_t s1 = nullptr, s2 = nullptr, s3 = nullptr;
    static cudaEvent_t evRoot = nullptr, evJ0 = nullptr, evJ1 = nullptr, evJ2 = nullptr;
    if (s1 == nullptr) {
        cudaStreamCreateWithFlags(&s1, cudaStreamNonBlocking);
        cudaStreamCreateWithFlags(&s2, cudaStreamNonBlocking);
        cudaStreamCreateWithFlags(&s3, cudaStreamNonBlocking);
        cudaEventCreateWithFlags(&evRoot, cudaEventDisableTiming);
        cudaEventCreateWithFlags(&evJ0, cudaEventDisableTiming);
        cudaEventCreateWithFlags(&evJ1, cudaEventDisableTiming);
        cudaEventCreateWithFlags(&evJ2, cudaEventDisableTiming);
    }
    cudaStream_t st[4] = { 0, s1, s2, s3 };
    cudaEvent_t evJ[3] = { evJ0, evJ1, evJ2 };

    // coalesced weight prep (tiled transposes)
    {
        dim3 thr(32, 8);
        prep_cplx<<<dim3(16, 8, Lc), thr>>>(BWr, BWi, w1, 256, 512, K1, 0,
                                            (size_t)256*512, (size_t)N1*K1);
        prep_real<<<dim3(16, 16, Lc), thr>>>(gW, w1, 512, K1, 1024,
                                             (size_t)512*512, (size_t)N1*K1);
        prep_cplx<<<dim3(8, 16, Lc), thr>>>(CWr, CWi, w2, 512, 256, K2, 0,
                                            (size_t)512*256, (size_t)N2*K2);
        prep_cplx<<<dim3(8, 8, Lc), thr>>>(DWr, DWi, w2, 256, 256, K2, 1024,
                                           (size_t)256*256, (size_t)N2*K2);
    }

    // fork
    cudaEventRecord(evRoot, st[0]);
    for (int b = 1; b < 4; b++) cudaStreamWaitEvent(st[b], evRoot, 0);

    // 4 independent per-batch pipelines
    for (int b = 0; b < 4; b++) {
        int mBase = b * Sc;
        for (int l = 0; l < Lc; l++) {
            const float* src = (l == 0) ? x : hbuf;

            ln_kernel<<<Sc/8, 256, 0, st[b]>>>(src, ng + l*Dc, nb + l*Dc, 0, nullptr, mBase);

            {   // GEMM1: Bx + gates (A = A1; K = 512)
                dim3 g(N1/128, Sc/128);
                mma_gemm<<<g, 256, GEMM_SMEM, st[b]>>>(a1, a1, w1 + (size_t)l*N1*K1, K1, 0, 0,
                                                       bx, gt, gb + (size_t)l*SDc,
                                                       nullptr, nullptr, mBase);
            }

            scan_fused<<<16, 1024, 0, st[b]>>>(l, theta, damp_p, h0, hfin, b);

            {   // GEMM2: y = C*hall + D*xn; K = 1536, hall 16 iters
                dim3 g(N2/128, Sc/128);
                mma_gemm<<<g, 256, GEMM_SMEM, st[b]>>>(a1, a2, w2 + (size_t)l*N2*K2, K2, 16, 1,
                                                       nullptr, nullptr, nullptr,
                                                       src, hbuf, mBase);
            }
        }
        // final LayerNorm for this quarter, on this stream
        ln_kernel<<<Sc/8, 256, 0, st[b]>>>(hbuf, og, ob, 1, out, mBase);
    }

    // join onto legacy stream (same as R14)
    for (int b = 1; b < 4; b++) {
        cudaEventRecord(evJ[b-1], st[b]);
        cudaStreamWaitEvent(st[0], evJ[b-1], 0);
    }
}

// round 17
// speedup vs baseline: 2.8512x; 1.0390x over previous
#include <cuda_runtime.h>
#include <cuda_fp16.h>
#include <math.h>
#include <cstdint>

#define Lc   8
#define Bc   4
#define Sc   2048
#define Dc   256
#define SDc  512
#define Mc   (Bc*Sc)      // 8192

// Karatsuba layouts
#define KA1  768          // A1: [xr(256) | xi(256) | xr+xi(256)]
#define KA2  1536         // A2: [hr(512) | hi(512) | hr+hi(512)]
#define N1   2048         // W1 rows: P1,P2,P3 blocks (512 each, K=256) + gate (512, K=512)
#define W1L  655360       // per-layer W1 elems: 3*512*256 + 512*512
#define N2   768          // W2 rows: 3 blocks of 256, K=768 each
#define W2L  589824       // 768*768
#define GATE_OFF 393216   // 3*512*256

// ----------------------------- device scratch --------------------------------
__device__ __half g_A1 [(size_t)Mc*KA1];
__device__ __half g_A2 [(size_t)Mc*KA2];
__device__ __half g_W1 [(size_t)Lc*W1L];
__device__ __half g_W2 [(size_t)Lc*W2L];
__device__ __half g_BxP[(size_t)Mc*1536];   // GEMM1 P planes [P1|P2|P3], pair-indexed
__device__ __half g_gt [(size_t)Mc*512];    // gates fp16
__device__ __half g_yP [(size_t)Mc*768];    // GEMM2 P planes [P1|P2|P3]
__device__ float  g_h  [(size_t)Mc*512];    // interleaved activation (residual chain)

// ----------------------------- helpers ----------------------------------------
__device__ __forceinline__ uint32_t s2u(const void* p){
    uint32_t a;
    asm("{ .reg .u64 t; cvta.to.shared.u64 t, %1; cvt.u32.u64 %0, t; }" : "=r"(a) : "l"(p));
    return a;
}
__device__ __forceinline__ void cpa16(uint32_t s, const void* g){
    asm volatile("cp.async.cg.shared.global [%0], [%1], 16;" :: "r"(s), "l"(g));
}
__device__ __forceinline__ uint32_t swz(uint32_t o){ return o ^ ((o >> 3) & 0x70); }

__device__ __forceinline__ void ldsm4(uint32_t* r, uint32_t addr){
    asm volatile("ldmatrix.sync.aligned.m8n8.x4.shared.b16 {%0,%1,%2,%3}, [%4];"
        : "=r"(r[0]), "=r"(r[1]), "=r"(r[2]), "=r"(r[3]) : "r"(addr));
}
__device__ __forceinline__ void mma16816(float* d, const uint32_t* a, const uint32_t* b){
    asm volatile("mma.sync.aligned.m16n8k16.row.col.f32.f16.f16.f32 "
        "{%0,%1,%2,%3}, {%4,%5,%6,%7}, {%8,%9}, {%0,%1,%2,%3};"
        : "+f"(d[0]), "+f"(d[1]), "+f"(d[2]), "+f"(d[3])
        : "r"(a[0]), "r"(a[1]), "r"(a[2]), "r"(a[3]), "r"(b[0]), "r"(b[1]));
}

// ----------------------------- weight prep ------------------------------------
// Karatsuba transpose: src R,I are [Ks,J] fp32. Writes three n-blocks:
//   D[(p*Nblk + j)*Wstr + kbase + k] = {R, I, R+I}[p] at [k][j]
__global__ void prep_kar(const float* __restrict__ srcR, const float* __restrict__ srcI,
                         __half* __restrict__ dst, int J_, int Nblk, int Wstr, int kbase,
                         size_t srcLS, size_t dstLS)
{
    __shared__ float sR[32][33], sI[32][33];
    int l = blockIdx.z;
    int j0 = blockIdx.x * 32, k0 = blockIdx.y * 32;
    int tx = threadIdx.x, ty = threadIdx.y;
    const float* R = srcR + (size_t)l * srcLS;
    const float* I = srcI + (size_t)l * srcLS;
    #pragma unroll
    for (int i = 0; i < 4; i++) {
        int k = k0 + ty + 8*i;
        sR[ty+8*i][tx] = R[(size_t)k * J_ + j0 + tx];
        sI[ty+8*i][tx] = I[(size_t)k * J_ + j0 + tx];
    }
    __syncthreads();
    __half* D = dst + (size_t)l * dstLS;
    size_t stride = (size_t)Nblk * Wstr;
    #pragma unroll
    for (int i = 0; i < 4; i++) {
        int jj = ty + 8*i;
        float r  = sR[tx][jj];
        float vi = sI[tx][jj];
        size_t a0 = (size_t)(j0 + jj) * Wstr + kbase + k0 + tx;
        D[a0]            = __float2half(r);
        D[a0 + stride]   = __float2half(vi);
        D[a0 + 2*stride] = __float2half(r + vi);
    }
}

// Real transpose: D[(nbase + c)*Kout + r] = src[r][c]
__global__ void prep_real(const float* __restrict__ src, __half* __restrict__ dst,
                          int Cn, int Kout, int nbase, size_t srcLS, size_t dstLS)
{
    __shared__ float s[32][33];
    int l = blockIdx.z;
    int c0 = blockIdx.x * 32, r0 = blockIdx.y * 32;
    int tx = threadIdx.x, ty = threadIdx.y;
    const float* S = src + (size_t)l * srcLS;
    #pragma unroll
    for (int i = 0; i < 4; i++)
        s[ty+8*i][tx] = S[(size_t)(r0+ty+8*i) * Cn + c0 + tx];
    __syncthreads();
    __half* D = dst + (size_t)l * dstLS;
    #pragma unroll
    for (int i = 0; i < 4; i++) {
        int cc = ty + 8*i;
        D[(size_t)(nbase + c0 + cc) * Kout + r0 + tx] = __float2half(s[tx][cc]);
    }
}

// ----------------------------- layer-0 LN (x -> A1 planes) ---------------------
__global__ void ln_first(const float* __restrict__ src,
                         const float* __restrict__ gw, const float* __restrict__ bw,
                         int mBase)
{
    int warp = threadIdx.x >> 5, L = threadIdx.x & 31;
    int m = mBase + blockIdx.x * 8 + warp;
    const float4* row = (const float4*)(src + (size_t)m * 512);
    float4 v[4];
    float sr=0.f, si=0.f, qr=0.f, qi=0.f;
    #pragma unroll
    for (int j=0;j<4;j++){
        v[j] = row[L + 32*j];
        sr += v[j].x + v[j].z;  si += v[j].y + v[j].w;
        qr += v[j].x*v[j].x + v[j].z*v[j].z;
        qi += v[j].y*v[j].y + v[j].w*v[j].w;
    }
    #pragma unroll
    for (int o=16;o>0;o>>=1){
        sr += __shfl_xor_sync(0xffffffffu, sr, o);
        si += __shfl_xor_sync(0xffffffffu, si, o);
        qr += __shfl_xor_sync(0xffffffffu, qr, o);
        qi += __shfl_xor_sync(0xffffffffu, qi, o);
    }
    const float inv = 1.f/256.f;
    float mur = sr*inv, mui = si*inv;
    float isr = rsqrtf(qr*inv - mur*mur + 1e-5f);
    float isi = rsqrtf(qi*inv - mui*mui + 1e-5f);

    __half* a1 = g_A1 + (size_t)m * KA1;
    #pragma unroll
    for (int j=0;j<4;j++){
        int f = L + 32*j;
        float2 g2 = ((const float2*)gw)[f];
        float2 b2 = ((const float2*)bw)[f];
        float nr0 = (v[j].x - mur)*isr*g2.x + b2.x;
        float ni0 = (v[j].y - mui)*isi*g2.x + b2.x;
        float nr1 = (v[j].z - mur)*isr*g2.y + b2.y;
        float ni1 = (v[j].w - mui)*isi*g2.y + b2.y;
        int d0 = 2*f;
        *(__half2*)(a1 + d0)       = __floats2half2_rn(nr0, nr1);
        *(__half2*)(a1 + 256 + d0) = __floats2half2_rn(ni0, ni1);
        *(__half2*)(a1 + 512 + d0) = __floats2half2_rn(nr0+ni0, nr1+ni1);
    }
}

// ----------------------------- combine + LN ------------------------------------
// h = resid + 0.1*out(y), y from yP Karatsuba planes; then LN(h).
// final==0: write h to hOut and LN -> A1 planes. final==1: LN -> outInter.
__global__ void combine_ln(const float* __restrict__ resid, const __half* __restrict__ yP,
                           const float* __restrict__ gw, const float* __restrict__ bw,
                           int final_mode, float* __restrict__ outInter,
                           float* __restrict__ hOut, int mBase)
{
    int warp = threadIdx.x >> 5, L = threadIdx.x & 31;
    int m = mBase + blockIdx.x * 8 + warp;
    const float4* rrow = (const float4*)(resid + (size_t)m * 512);
    const __half* yrow = yP + (size_t)m * 768;
    float4 v[4];
    float sr=0.f, si=0.f, qr=0.f, qi=0.f;
    #pragma unroll
    for (int j=0;j<4;j++){
        int f = L + 32*j;
        float4 r4 = rrow[f];
        float2 f1 = __half22float2(*(const __half2*)(yrow + 2*f));
        float2 f2 = __half22float2(*(const __half2*)(yrow + 256 + 2*f));
        float2 f3 = __half22float2(*(const __half2*)(yrow + 512 + 2*f));
        float yr0 = f1.x - f2.x, yi0 = f3.x - f1.x - f2.x;
        float yr1 = f1.y - f2.y, yi1 = f3.y - f1.y - f2.y;
        v[j].x = r4.x + 0.1f*(yr0*yr0 + yr0);
        v[j].y = r4.y + 0.1f*(yr0*yi0 + yi0);
        v[j].z = r4.z + 0.1f*(yr1*yr1 + yr1);
        v[j].w = r4.w + 0.1f*(yr1*yi1 + yi1);
        sr += v[j].x + v[j].z;  si += v[j].y + v[j].w;
        qr += v[j].x*v[j].x + v[j].z*v[j].z;
        qi += v[j].y*v[j].y + v[j].w*v[j].w;
    }
    #pragma unroll
    for (int o=16;o>0;o>>=1){
        sr += __shfl_xor_sync(0xffffffffu, sr, o);
        si += __shfl_xor_sync(0xffffffffu, si, o);
        qr += __shfl_xor_sync(0xffffffffu, qr, o);
        qi += __shfl_xor_sync(0xffffffffu, qi, o);
    }
    const float inv = 1.f/256.f;
    float mur = sr*inv, mui = si*inv;
    float isr = rsqrtf(qr*inv - mur*mur + 1e-5f);
    float isi = rsqrtf(qi*inv - mui*mui + 1e-5f);

    __half* a1 = g_A1 + (size_t)m * KA1;
    float* hrow = final_mode ? nullptr : (hOut + (size_t)m*512);
    float* orow = final_mode ? (outInter + (size_t)m*512) : nullptr;
    #pragma unroll
    for (int j=0;j<4;j++){
        int f = L + 32*j;
        float2 g2 = ((const float2*)gw)[f];
        float2 b2 = ((const float2*)bw)[f];
        float nr0 = (v[j].x - mur)*isr*g2.x + b2.x;
        float ni0 = (v[j].y - mui)*isi*g2.x + b2.x;
        float nr1 = (v[j].z - mur)*isr*g2.y + b2.y;
        float ni1 = (v[j].w - mui)*isi*g2.y + b2.y;
        if (final_mode) {
            float4 o4; o4.x=nr0; o4.y=ni0; o4.z=nr1; o4.w=ni1;
            ((float4*)orow)[f] = o4;
        } else {
            ((float4*)hrow)[f] = v[j];
            int d0 = 2*f;
            *(__half2*)(a1 + d0)       = __floats2half2_rn(nr0, nr1);
            *(__half2*)(a1 + 256 + d0) = __floats2half2_rn(ni0, ni1);
            *(__half2*)(a1 + 512 + d0) = __floats2half2_rn(nr0+ni0, nr1+ni1);
        }
    }
}

// ----------------------------- fused scan (per-batch-quarter) ------------------
__global__ void __launch_bounds__(1024, 1)
scan_fused(int layer, const float* __restrict__ theta, const float* __restrict__ damp,
           const float* __restrict__ h0, float* __restrict__ hfin, int b)
{
    __shared__ float4 scarry[32][33];
    __shared__ float2 sstart[32][33];
    int tid = threadIdx.x;
    int w = tid >> 5, lane = tid & 31;
    int sdt = blockIdx.x;
    int sd = sdt*32 + lane;

    float th = theta[layer*SDc+sd], dp = damp[layer*SDc+sd];
    float dm = 0.5f + 0.5f/(1.f+expf(-dp));
    float cd = cosf(th)*dm, sn = sinf(th)*dm;

    int base_row = b*Sc + w*64;

    // Phase 1: chunk carry
    float Ar=1.f, Ai=0.f, Br=0.f, Bi=0.f;
    #pragma unroll 4
    for (int s=0;s<64;s++){
        int row = base_row + s;
        float g = __half2float(g_gt[(size_t)row*512+sd]);
        const __half* bp = g_BxP + (size_t)row*1536 + sd;
        float P1 = __half2float(bp[0]);
        float P2 = __half2float(bp[512]);
        float P3 = __half2float(bp[1024]);
        float bxr = P1 - P2, bxi = P3 - P1 - P2;
        float og = 1.f - g;
        float ar = og*cd, ai = og*sn;
        float nAr = ar*Ar - ai*Ai, nAi = ar*Ai + ai*Ar;
        float nBr = ar*Br - ai*Bi + g*bxr;
        float nBi = ar*Bi + ai*Br + g*bxi;
        Ar=nAr; Ai=nAi; Br=nBr; Bi=nBi;
    }
    float4 cv; cv.x=Ar; cv.y=Ai; cv.z=Br; cv.w=Bi;
    scarry[w][lane] = cv;
    __syncthreads();

    // Phase 2: prefix over chunks
    if (w == 0) {
        size_t hidx = ((size_t)(layer*Bc+b)*SDc + sd)*2;
        float hr = h0[hidx], hi = h0[hidx+1];
        #pragma unroll
        for (int c=0;c<32;c++){
            float2 s2; s2.x=hr; s2.y=hi;
            sstart[c][lane] = s2;
            float4 cc = scarry[c][lane];
            float nr = cc.x*hr - cc.y*hi + cc.z;
            float ni = cc.x*hi + cc.y*hr + cc.w;
            hr=nr; hi=ni;
        }
        hfin[hidx]   = hr;
        hfin[hidx+1] = hi;
    }
    __syncthreads();

    // Phase 3: rescan, emit A2 planes [hr | hi | hr+hi]
    float2 st0 = sstart[w][lane];
    float hr = st0.x, hi = st0.y;
    #pragma unroll 4
    for (int s=0;s<64;s++){
        int row = base_row + s;
        float g = __half2float(g_gt[(size_t)row*512+sd]);
        const __half* bp = g_BxP + (size_t)row*1536 + sd;
        float P1 = __half2float(bp[0]);
        float P2 = __half2float(bp[512]);
        float P3 = __half2float(bp[1024]);
        float bxr = P1 - P2, bxi = P3 - P1 - P2;
        float tr = hr*cd - hi*sn, ti = hr*sn + hi*cd;
        float og = 1.f - g;
        hr = fmaf(g, bxr, og*tr);
        hi = fmaf(g, bxi, og*ti);
        __half* a2 = g_A2 + (size_t)row*KA2;
        a2[sd]        = __float2half(hr);
        a2[512+sd]    = __float2half(hi);
        a2[1024+sd]   = __float2half(hr+hi);
    }
}

// ----------------------------- HMMA GEMM (templated on mode) -------------------
// MODE 0 (GEMM1): N=2048, block b = n0>>9: b<3: K=256, A=A1+b*256, W rows (n)*256.
//   b=3 (gate): K=512, A=A1, W at GATE_OFF rows (n-1536)*512. Out: BxP / gates.
// MODE 1 (GEMM2): N=768, p=n0>>8, K=768: ki<8 -> A2+p*512 (C part), else
//   A1+p*256 (D part). W rows n*768. Out: yP fp16.
#define ST 3
#define STAGE_BYTES 32768
#define GEMM_SMEM (ST*STAGE_BYTES) // 96KB -> 2 CTAs/SM

template<int MODE>
__global__ void __launch_bounds__(256, 2)
mma_gemm(const __half* __restrict__ A1p, const __half* __restrict__ A2p,
         const __half* __restrict__ W,
         __half* __restrict__ oBxP, __half* __restrict__ oGt, const float* __restrict__ gb,
         __half* __restrict__ oYP, int mBase)
{
    extern __shared__ char smem[];
    uint32_t sb = s2u(smem);
    int tid = threadIdx.x, wid = tid >> 5, L = tid & 31;
    int m0 = mBase + blockIdx.y * 128, n0 = blockIdx.x * 128;

    int NK, Wstr, nloc, p = 0, blk = 0;
    const __half* Wb;
    if (MODE == 0) {
        blk = n0 >> 9;
        if (blk < 3) { NK = 4; Wstr = 256; Wb = W; nloc = n0; }
        else { NK = 8; Wstr = 512; Wb = W + GATE_OFF; nloc = n0 - 1536; }
    } else {
        NK = 12; Wstr = 768; Wb = W; nloc = n0; p = n0 >> 8;
    }

    // ---- A chunks ----
    uint32_t cA[4], soffA[4];
    size_t aOff1[4];          // offset into A1 (incl. plane)
    size_t aOff2[4];          // offset into A2 (MODE 1 only)
    #pragma unroll
    for (int i = 0; i < 4; i++) {
        int q = tid + i*256;
        int r = q >> 3, c = q & 7;
        cA[i] = (uint32_t)(c * 8);
        soffA[i] = swz((uint32_t)(r*128 + c*16));
        int row = m0 + r;
        if (MODE == 0) aOff1[i] = (size_t)row*KA1 + (blk < 3 ? blk*256 : 0) + cA[i];
        else {
            aOff1[i] = (size_t)row*KA1 + p*256 + cA[i];
            aOff2[i] = (size_t)row*KA2 + p*512 + cA[i];
        }
    }
    // ---- B chunks ----
    const __half* gBp[4]; uint32_t soffB[4];
    #pragma unroll
    for (int i = 0; i < 4; i++) {
        int q = (tid + (i+4)*256) & 1023;
        int r = q >> 3, c = q & 7;
        gBp[i] = Wb + (size_t)(nloc + r)*Wstr + c*8;
        soffB[i] = 16384u + swz((uint32_t)(r*128 + c*16));
    }

    // ---- ldmatrix lane addressing ----
    int wm = wid >> 2, wn = wid & 3;
    int rowA0 = wm*64 + (L & 7) + ((L >> 3) & 1) * 8;
    uint32_t aBase = (uint32_t)rowA0 * 128; uint32_t aS = (uint32_t)(rowA0 & 7);
    uint32_t aC = (uint32_t)(L >> 4);
    int rowB0 = wn*32 + (L & 7) + ((L >> 4) & 1) * 8;
    uint32_t bBase = 16384u + (uint32_t)rowB0 * 128; uint32_t bS = (uint32_t)(rowB0 & 7);
    uint32_t bC = (uint32_t)((L >> 3) & 1);

    float c[4][4][4];
    #pragma unroll
    for (int i=0;i<4;i++)
        #pragma unroll
        for (int j=0;j<4;j++)
            #pragma unroll
            for (int e=0;e<4;e++) c[i][j][e] = 0.f;

    auto load_stage = [&](int ki, uint32_t st){
        if (MODE == 1 && ki < 8) {
            uint32_t koff = (uint32_t)(ki << 6);
            #pragma unroll
            for (int i = 0; i < 4; i++)
                cpa16(st + soffA[i], A2p + aOff2[i] + koff);
        } else {
            int kj = (MODE == 1) ? ki - 8 : ki;
            uint32_t koff = (uint32_t)(kj << 6);
            #pragma unroll
            for (int i = 0; i < 4; i++)
                cpa16(st + soffA[i], A1p + aOff1[i] + koff);
        }
        uint32_t kb = (uint32_t)(ki << 6);
        #pragma unroll
        for (int i = 0; i < 4; i++)
            cpa16(st + soffB[i], gBp[i] + kb);
    };

    #pragma unroll
    for (int s = 0; s < ST-1; s++) {
        if (s < NK) load_stage(s, sb + s*STAGE_BYTES);
        asm volatile("cp.async.commit_group;" ::: "memory");
    }

    for (int ki = 0; ki < NK; ki++) {
        asm volatile("cp.async.wait_group %0;" :: "n"(ST-2) : "memory");
        __syncthreads();

        uint32_t st = sb + (uint32_t)(ki % ST) * STAGE_BYTES;
        #pragma unroll
        for (int kk = 0; kk < 4; kk++) {
            uint32_t a[4][4], b[2][4];
            uint32_t ca = (uint32_t)(kk*2);
            #pragma unroll
            for (int mt = 0; mt < 4; mt++)
                ldsm4(a[mt], st + aBase + (uint32_t)mt*2048 + (((ca + aC) ^ aS) << 4));
            #pragma unroll
            for (int bt = 0; bt < 2; bt++)
                ldsm4(b[bt], st + bBase + (uint32_t)bt*2048 + (((ca + bC) ^ bS) << 4));
            #pragma unroll
            for (int mt = 0; mt < 4; mt++)
                #pragma unroll
                for (int nt = 0; nt < 4; nt++)
                    mma16816(c[mt][nt], a[mt], &b[nt>>1][(nt&1)*2]);
        }

        int ls = ki + ST - 1;
        if (ls < NK) load_stage(ls, sb + (uint32_t)(ls % ST) * STAGE_BYTES);
        asm volatile("cp.async.commit_group;" ::: "memory");
    }

    // ---- epilogue ----
    int lrow = L >> 2, lcol = (L & 3) * 2;
    int mRow = m0 + wm*64 + lrow;
    int nCol = n0 + wn*32 + lcol;
    #pragma unroll
    for (int mt = 0; mt < 4; mt++) {
        #pragma unroll
        for (int nt = 0; nt < 4; nt++) {
            int row = mRow + mt*16;
            int col = nCol + nt*8;
            float* cc = c[mt][nt];
            if (MODE == 0) {
                if (col < 1536) {
                    *(__half2*)&oBxP[(size_t)row*1536 + col]     = __floats2half2_rn(cc[0], cc[1]);
                    *(__half2*)&oBxP[(size_t)(row+8)*1536 + col] = __floats2half2_rn(cc[2], cc[3]);
                } else {
                    int gc = col - 1536;
                    float b0 = gb[gc], b1 = gb[gc+1];
                    float g00 = 1.f/(1.f+expf(-(cc[0]+b0)));
                    float g01 = 1.f/(1.f+expf(-(cc[1]+b1)));
                    float g10 = 1.f/(1.f+expf(-(cc[2]+b0)));
                    float g11 = 1.f/(1.f+expf(-(cc[3]+b1)));
                    *(__half2*)&oGt[(size_t)row*512 + gc]     = __floats2half2_rn(g00, g01);
                    *(__half2*)&oGt[(size_t)(row+8)*512 + gc] = __floats2half2_rn(g10, g11);
                }
            } else {
                *(__half2*)&oYP[(size_t)row*768 + col]     = __floats2half2_rn(cc[0], cc[1]);
                *(__half2*)&oYP[(size_t)(row+8)*768 + col] = __floats2half2_rn(cc[2], cc[3]);
            }
        }
    }
}

// ----------------------------- host ---------------------------------------------
extern "C" void kernel_launch(void* const* d_in, const int* in_sizes, int n_in,
                              void* d_out, int out_size)
{
    const float* x      = (const float*)d_in[0];
    const float* h0     = (const float*)d_in[1];
    const float* theta  = (const float*)d_in[2];
    const float* damp_p = (const float*)d_in[3];
    const float* BWr    = (const float*)d_in[4];
    const float* BWi    = (const float*)d_in[5];
    const float* CWr    = (const float*)d_in[6];
    const float* CWi    = (const float*)d_in[7];
    const float* DWr    = (const float*)d_in[8];
    const float* DWi    = (const float*)d_in[9];
    const float* gW     = (const float*)d_in[10];
    const float* gb     = (const float*)d_in[11];
    const float* ng     = (const float*)d_in[12];
    const float* nb     = (const float*)d_in[13];
    const float* og     = (const float*)d_in[14];
    const float* ob     = (const float*)d_in[15];
    float* out = (float*)d_out;

    cudaFuncSetAttribute(mma_gemm<0>, cudaFuncAttributeMaxDynamicSharedMemorySize, GEMM_SMEM);
    cudaFuncSetAttribute(mma_gemm<1>, cudaFuncAttributeMaxDynamicSharedMemorySize, GEMM_SMEM);

    __half *a1, *a2, *w1, *w2, *bxp, *gt, *yp;
    float *hbuf;
    cudaGetSymbolAddress((void**)&a1, g_A1);
    cudaGetSymbolAddress((void**)&a2, g_A2);
    cudaGetSymbolAddress((void**)&w1, g_W1);
    cudaGetSymbolAddress((void**)&w2, g_W2);
    cudaGetSymbolAddress((void**)&bxp, g_BxP);
    cudaGetSymbolAddress((void**)&gt, g_gt);
    cudaGetSymbolAddress((void**)&yp, g_yP);
    cudaGetSymbolAddress((void**)&hbuf, g_h);

    float* hfin = out + (size_t)Mc*Dc*2;

    // R14/R16-proven stream/event topology: created once, reused on capture.
    static cudaStream_t s1 = nullptr, s2 = nullptr, s3 = nullptr;
    static cudaEvent_t evRoot = nullptr, evJ0 = nullptr, evJ1 = nullptr, evJ2 = nullptr;
    if (s1 == nullptr) {
        cudaStreamCreateWithFlags(&s1, cudaStreamNonBlocking);
        cudaStreamCreateWithFlags(&s2, cudaStreamNonBlocking);
        cudaStreamCreateWithFlags(&s3, cudaStreamNonBlocking);
        cudaEventCreateWithFlags(&evRoot, cudaEventDisableTiming);
        cudaEventCreateWithFlags(&evJ0, cudaEventDisableTiming);
        cudaEventCreateWithFlags(&evJ1, cudaEventDisableTiming);
        cudaEventCreateWithFlags(&evJ2, cudaEventDisableTiming);
    }
    cudaStream_t st[4] = { 0, s1, s2, s3 };
    cudaEvent_t evJ[3] = { evJ0, evJ1, evJ2 };

    // weight prep (coalesced Karatsuba transposes)
    {
        dim3 thr(32, 8);
        // W1 B-proj: R,I [256,512] -> 3 blocks of rows 512 x K256
        prep_kar<<<dim3(16, 8, Lc), thr>>>(BWr, BWi, w1, 512, 512, 256, 0,
                                           (size_t)256*512, (size_t)W1L);
        // W1 gate: gW [512,512] -> rows 512 x K512 at GATE_OFF
        prep_real<<<dim3(16, 16, Lc), thr>>>(gW, w1 + GATE_OFF, 512, 512, 0,
                                             (size_t)512*512, (size_t)W1L);
        // W2 C-part: [512,256] -> 3 blocks rows 256 x K768 (k 0..511)
        prep_kar<<<dim3(8, 16, Lc), thr>>>(CWr, CWi, w2, 256, 256, 768, 0,
                                           (size_t)512*256, (size_t)W2L);
        // W2 D-part: [256,256] -> same blocks, k 512..767
        prep_kar<<<dim3(8, 8, Lc), thr>>>(DWr, DWi, w2, 256, 256, 768, 512,
                                          (size_t)256*256, (size_t)W2L);
    }

    // fork
    cudaEventRecord(evRoot, st[0]);
    for (int b = 1; b < 4; b++) cudaStreamWaitEvent(st[b], evRoot, 0);

    // 4 independent per-batch pipelines
    for (int b = 0; b < 4; b++) {
        int mBase = b * Sc;
        for (int l = 0; l < Lc; l++) {
            if (l == 0)
                ln_first<<<Sc/8, 256, 0, st[b]>>>(x, ng, nb, mBase);
            else
                combine_ln<<<Sc/8, 256, 0, st[b]>>>((l == 1) ? x : hbuf, yp,
                                                    ng + l*Dc, nb + l*Dc, 0,
                                                    nullptr, hbuf, mBase);

            {   // GEMM1: Karatsuba B-proj P-planes + gates
                dim3 g(N1/128, Sc/128);
                mma_gemm<0><<<g, 256, GEMM_SMEM, st[b]>>>(a1, a2, w1 + (size_t)l*W1L,
                                                          bxp, gt, gb + (size_t)l*SDc,
                                                          nullptr, mBase);
            }

            scan_fused<<<16, 1024, 0, st[b]>>>(l, theta, damp_p, h0, hfin, b);

            {   // GEMM2: Karatsuba C+D P-planes
                dim3 g(N2/128, Sc/128);
                mma_gemm<1><<<g, 256, GEMM_SMEM, st[b]>>>(a1, a2, w2 + (size_t)l*W2L,
                                                          nullptr, nullptr, nullptr,
                                                          yp, mBase);
            }
        }
        // final: h = h7 + 0.1*out(y7); LN -> out
        combine_ln<<<Sc/8, 256, 0, st[b]>>>(hbuf, yp, og, ob, 1, out, nullptr, mBase);
    }

    // join onto legacy stream
    for (int b = 1; b < 4; b++) {
        cudaEventRecord(evJ[b-1], st[b]);
        cudaStreamWaitEvent(st[0], evJ[b-1], 0);
    }
}